// round 4
// baseline (speedup 1.0000x reference)
#include <cuda_runtime.h>
#include <cuda.h>
#include <cstdint>
#include <math.h>

// ---------------- problem dims ----------------
#define NB 16384
#define ND 2048
#define NH 2048
#define NE 6
#define NC 1024
#define NEH 12288       // E*H
// ---------------- tiling ----------------------
#define TM 128
#define TN 128
#define TK 32                      // k floats per stage = 128 bytes
#define STAGES 4
#define A_BYTES (TM*TK*4)          // 16384
#define B_BYTES (TN*TK*4)          // 16384
#define STAGE_BYTES (A_BYTES + B_BYTES)     // 32768
#define DATA_OFF 1024
#define SMEM_TOTAL (DATA_OFF + STAGES*STAGE_BYTES)   // 132096

// ---------------- scratch (device globals; no allocation) -----------------
__device__ float g_xr [(size_t)NB * ND];     // x rounded to tf32
__device__ float g_w1r[(size_t)NEH * ND];    // W1 rounded, [E*H, D] K-major
__device__ float g_w2r[(size_t)NC * NEH];    // W2 permuted+rounded, [C, E*H] K-major
__device__ float g_h  [(size_t)NB * NEH];    // gw-scaled gelu(xW1+b1), tf32

// ---------------- ptx helpers ----------------------------------------------
__device__ __forceinline__ uint32_t smem_u32(const void* p) {
    uint32_t a;
    asm("{ .reg .u64 t; cvta.to.shared.u64 t, %1; cvt.u32.u64 %0, t; }"
        : "=r"(a) : "l"(p));
    return a;
}
__device__ __forceinline__ float rna_tf32(float f) {
    uint32_t u; asm("cvt.rna.tf32.f32 %0, %1;" : "=r"(u) : "f"(f));
    return __uint_as_float(u);
}
__device__ __forceinline__ uint32_t lds32(uint32_t addr) {
    uint32_t v; asm("ld.shared.b32 %0, [%1];" : "=r"(v) : "r"(addr));
    return v;
}

#define MBARRIER_INIT(addr, count) \
    asm volatile("mbarrier.init.shared.b64 [%0], %1;" \
        :: "r"((uint32_t)(addr)), "r"((uint32_t)(count)) : "memory")
#define MBARRIER_EXPECT_TX(addr, bytes) \
    asm volatile("mbarrier.arrive.expect_tx.shared.b64 _, [%0], %1;" \
        :: "r"((uint32_t)(addr)), "r"((uint32_t)(bytes)) : "memory")
#define MBARRIER_ARRIVE(addr) \
    asm volatile("mbarrier.arrive.shared.b64 _, [%0];" \
        :: "r"((uint32_t)(addr)) : "memory")

#define MBARRIER_WAIT_PARITY(mbar_smem_addr, phase_parity) do { \
    uint32_t _mbar = (uint32_t)(mbar_smem_addr); \
    uint32_t _parity = (uint32_t)(phase_parity); \
    uint32_t _done; \
    asm volatile("{\n\t.reg .pred p;\n\t" \
        "mbarrier.try_wait.parity.acquire.cta.shared::cta.b64 p, [%1], %2;\n\t" \
        "selp.b32 %0, 1, 0, p;\n\t}" \
        : "=r"(_done) : "r"(_mbar), "r"(_parity) : "memory"); \
    if (!_done) { \
        asm volatile("{\n\t.reg .pred P1;\n\t" \
            "WAIT_LOOP_%=:\n\t" \
            "mbarrier.try_wait.parity.acquire.cta.shared::cta.b64 P1, [%0], %1, 0x989680;\n\t" \
            "@P1 bra.uni WAIT_DONE_%=;\n\t" \
            "bra.uni WAIT_LOOP_%=;\n\t" \
            "WAIT_DONE_%=:\n\t}" \
            :: "r"(_mbar), "r"(_parity) : "memory"); \
    } \
} while (0)

#define MBARRIER_WAIT_PARITY_RELAXED(mbar_smem_addr, phase_parity) do { \
    uint32_t _mbar = (uint32_t)(mbar_smem_addr); \
    uint32_t _parity = (uint32_t)(phase_parity); \
    uint32_t _done; \
    asm volatile("{\n\t.reg .pred p;\n\t" \
        "mbarrier.try_wait.parity.relaxed.cta.shared::cta.b64 p, [%1], %2, 0x989680;\n\t" \
        "selp.b32 %0, 1, 0, p;\n\t}" \
        : "=r"(_done) : "r"(_mbar), "r"(_parity) : "memory"); \
    if (!_done) { \
        asm volatile("{\n\t.reg .pred P1;\n\t" \
            "WAIT_LOOP_%=:\n\t" \
            "mbarrier.try_wait.parity.relaxed.cta.shared::cta.b64 P1, [%0], %1, 0x989680;\n\t" \
            "@P1 bra.uni WAIT_DONE_%=;\n\t" \
            "bra.uni WAIT_LOOP_%=;\n\t" \
            "WAIT_DONE_%=:\n\t}" \
            :: "r"(_mbar), "r"(_parity) : "memory"); \
    } \
} while (0)

#define TMA2D(smem_addr, map_ptr, cx, cy, mbar) \
    asm volatile("cp.async.bulk.tensor.2d.shared::cta.global.tile.mbarrier::complete_tx::bytes " \
        "[%0], [%1, {%2, %3}], [%4];" \
        :: "r"((uint32_t)(smem_addr)), "l"(map_ptr), "r"((int)(cx)), "r"((int)(cy)), \
           "r"((uint32_t)(mbar)) : "memory")

// m16n8k8 tf32 HMMA, D += A*B (D doubles as C)
__device__ __forceinline__ void mma_tf32(float* d, const uint32_t* a, const uint32_t* b) {
    asm volatile("mma.sync.aligned.m16n8k8.row.col.f32.tf32.tf32.f32 "
        "{%0,%1,%2,%3}, {%4,%5,%6,%7}, {%8,%9}, {%0,%1,%2,%3};"
        : "+f"(d[0]), "+f"(d[1]), "+f"(d[2]), "+f"(d[3])
        : "r"(a[0]), "r"(a[1]), "r"(a[2]), "r"(a[3]), "r"(b[0]), "r"(b[1]));
}

__device__ __forceinline__ float gelu_exact(float x) {
    return 0.5f * x * (1.f + erff(x * 0.70710678118654752f));
}

// ---------------- elementwise pre-pass kernels ------------------------------
__global__ void k_rnd(const float4* __restrict__ in, float4* __restrict__ out, int n4) {
    int i = blockIdx.x * blockDim.x + threadIdx.x;
    int stride = gridDim.x * blockDim.x;
    for (; i < n4; i += stride) {
        float4 v = in[i];
        v.x = rna_tf32(v.x); v.y = rna_tf32(v.y);
        v.z = rna_tf32(v.z); v.w = rna_tf32(v.w);
        out[i] = v;
    }
}

// W2 [E,C,H] -> g_w2r [C, E*H] (permute + round); float4 over H
__global__ void k_w2perm(const float* __restrict__ W2, float* __restrict__ out) {
    int i = blockIdx.x * blockDim.x + threadIdx.x;   // one float4 of output
    const int H4 = NH / 4;
    const int TOT = NC * NEH / 4;
    if (i >= TOT) return;
    int h4 = i % H4;
    int r = i / H4;
    int e = r % NE;
    int c = r / NE;
    size_t src = ((size_t)(e * NC + c) * NH) / 4 + h4;
    float4 v = ((const float4*)W2)[src];
    v.x = rna_tf32(v.x); v.y = rna_tf32(v.y);
    v.z = rna_tf32(v.z); v.w = rna_tf32(v.w);
    ((float4*)out)[i] = v;
}

// ---------------- gate: fp32 logits + top-3 softmax -------------------------
__global__ void k_gate(const float* __restrict__ x, const float* __restrict__ gW,
                       const float* __restrict__ gb, float* __restrict__ gwout) {
    int row = blockIdx.x * 8 + (threadIdx.x >> 5);
    int lane = threadIdx.x & 31;
    const float* xr = x + (size_t)row * ND;
    float acc[NE];
    #pragma unroll
    for (int e = 0; e < NE; e++) acc[e] = 0.f;
    for (int d = lane * 4; d < ND; d += 128) {
        float4 xv = *(const float4*)(xr + d);
        #pragma unroll
        for (int e = 0; e < NE; e++) {
            float4 wv = *(const float4*)(gW + (size_t)e * ND + d);
            acc[e] += xv.x * wv.x + xv.y * wv.y + xv.z * wv.z + xv.w * wv.w;
        }
    }
    #pragma unroll
    for (int e = 0; e < NE; e++)
        #pragma unroll
        for (int o = 16; o > 0; o >>= 1)
            acc[e] += __shfl_xor_sync(0xFFFFFFFF, acc[e], o);
    float l[NE];
    #pragma unroll
    for (int e = 0; e < NE; e++) l[e] = acc[e] + gb[e];
    bool used[NE] = {false, false, false, false, false, false};
    float mx = -3.4e38f;
    for (int t = 0; t < 3; t++) {
        float best = -3.4e38f; int bi = 0;
        #pragma unroll
        for (int e = 0; e < NE; e++)
            if (!used[e] && l[e] > best) { best = l[e]; bi = e; }
        used[bi] = true;
        if (t == 0) mx = best;
    }
    float s = 0.f;
    #pragma unroll
    for (int e = 0; e < NE; e++) if (used[e]) s += expf(l[e] - mx);
    float inv = 1.f / s;
    if (lane < NE)
        gwout[(size_t)row * NE + lane] = used[lane] ? expf(l[lane] - mx) * inv : 0.f;
}

// ---------------- GEMM via mma.sync tf32 + TMA pipeline ---------------------
// MODE 0: D[128,128] = x @ W1^T tile ; epi: +b1, gelu, *gw[row][e], rna -> g_h
// MODE 1: D[128,128] = h @ W2'^T tile; epi: + sum_e gw_e*b2[e][c] -> d_out
template <int MODE>
__global__ void __launch_bounds__(256, 1) k_gemm(
    const __grid_constant__ CUtensorMap amap,
    const __grid_constant__ CUtensorMap bmap,
    const float* __restrict__ bias,
    const float* __restrict__ gw,
    float* __restrict__ outp,
    int kiters)
{
    extern __shared__ __align__(1024) char smem[];
    const uint32_t sb = smem_u32(smem);
    const int tid  = threadIdx.x;
    const int lane = tid & 31;
    const int wid  = tid >> 5;
    const int wm   = wid >> 2;      // 0..1  (64-row slab)
    const int wn   = wid & 3;       // 0..3  (32-col slab)
    const int g    = lane >> 2;     // group id (0..7)
    const int t4   = lane & 3;
    const int m0 = blockIdx.y * TM;
    const int n0 = blockIdx.x * TN;

    const uint32_t FULL0  = sb;
    const uint32_t EMPTY0 = sb + 64;

    if (tid == 0) {
        #pragma unroll
        for (int s = 0; s < STAGES; s++) {
            MBARRIER_INIT(FULL0  + s * 8, 1);
            MBARRIER_INIT(EMPTY0 + s * 8, 8);   // one arrive per warp
        }
    }
    __syncthreads();

    float acc[4][4][4];
    #pragma unroll
    for (int mi = 0; mi < 4; mi++)
        #pragma unroll
        for (int ni = 0; ni < 4; ni++)
            #pragma unroll
            for (int q = 0; q < 4; q++) acc[mi][ni][q] = 0.f;

    int se = 0, pe = 1;   // producer cursor, phase 1: first STAGES waits pass
    #define ISSUE(i) do { \
        MBARRIER_WAIT_PARITY_RELAXED(EMPTY0 + se * 8, pe); \
        uint32_t fb = FULL0 + se * 8; \
        MBARRIER_EXPECT_TX(fb, STAGE_BYTES); \
        uint32_t dst = sb + DATA_OFF + se * STAGE_BYTES; \
        TMA2D(dst,            &amap, (i) * TK, m0, fb); \
        TMA2D(dst + A_BYTES,  &bmap, (i) * TK, n0, fb); \
        if (++se == STAGES) { se = 0; pe ^= 1; } \
    } while (0)

    if (tid == 0) {
        int pre = (kiters < STAGES - 1) ? kiters : (STAGES - 1);
        for (int i = 0; i < pre; i++) ISSUE(i);
    }

    int sc = 0, pc = 0;
    for (int kt = 0; kt < kiters; kt++) {
        MBARRIER_WAIT_PARITY(FULL0 + sc * 8, pc);
        if (tid == 0 && kt + STAGES - 1 < kiters) ISSUE(kt + STAGES - 1);

        uint32_t aB = sb + DATA_OFF + sc * STAGE_BYTES;
        uint32_t bB = aB + A_BYTES;
        #pragma unroll
        for (int kk = 0; kk < 4; kk++) {        // 4 x k8 steps = TK 32
            uint32_t a[4][4], b[4][2];
            #pragma unroll
            for (int mi = 0; mi < 4; mi++) {
                int r0 = wm * 64 + mi * 16 + g;         // and r0+8
                uint32_t sw = (uint32_t)((r0 & 7) << 4);
                uint32_t c0 = (uint32_t)(kk * 32 + t4 * 4);
                a[mi][0] = lds32(aB + r0 * 128       + (c0        ^ sw));
                a[mi][1] = lds32(aB + (r0 + 8) * 128 + (c0        ^ sw));
                a[mi][2] = lds32(aB + r0 * 128       + ((c0 + 16) ^ sw));
                a[mi][3] = lds32(aB + (r0 + 8) * 128 + ((c0 + 16) ^ sw));
            }
            #pragma unroll
            for (int ni = 0; ni < 4; ni++) {
                int n = wn * 32 + ni * 8 + g;
                uint32_t sw = (uint32_t)((n & 7) << 4);
                uint32_t k0 = (uint32_t)(kk * 32 + t4 * 4);
                b[ni][0] = lds32(bB + n * 128 + (k0        ^ sw));
                b[ni][1] = lds32(bB + n * 128 + ((k0 + 16) ^ sw));
            }
            #pragma unroll
            for (int mi = 0; mi < 4; mi++)
                #pragma unroll
                for (int ni = 0; ni < 4; ni++)
                    mma_tf32(acc[mi][ni], a[mi], b[ni]);
        }
        if (lane == 0) MBARRIER_ARRIVE(EMPTY0 + sc * 8);
        if (++sc == STAGES) { sc = 0; pc ^= 1; }
    }
    #undef ISSUE

    // ---------------- epilogue (register accumulators) ----------------------
    if (MODE == 0) {
        const int e = n0 >> 11;                 // 128-wide tile within one expert
        #pragma unroll
        for (int mi = 0; mi < 4; mi++) {
            int r = m0 + wm * 64 + mi * 16 + g;
            float gw0 = __ldg(&gw[(size_t)r * NE + e]);
            float gw1 = __ldg(&gw[(size_t)(r + 8) * NE + e]);
            #pragma unroll
            for (int ni = 0; ni < 4; ni++) {
                int c = n0 + wn * 32 + ni * 8 + t4 * 2;
                float bb0 = __ldg(&bias[c]);
                float bb1 = __ldg(&bias[c + 1]);
                float v0 = rna_tf32(gelu_exact(acc[mi][ni][0] + bb0) * gw0);
                float v1 = rna_tf32(gelu_exact(acc[mi][ni][1] + bb1) * gw0);
                float v2 = rna_tf32(gelu_exact(acc[mi][ni][2] + bb0) * gw1);
                float v3 = rna_tf32(gelu_exact(acc[mi][ni][3] + bb1) * gw1);
                *(float2*)(outp + (size_t)r * NEH + c)       = make_float2(v0, v1);
                *(float2*)(outp + (size_t)(r + 8) * NEH + c) = make_float2(v2, v3);
            }
        }
    } else {
        #pragma unroll
        for (int mi = 0; mi < 4; mi++) {
            int r = m0 + wm * 64 + mi * 16 + g;
            float gr0[NE], gr1[NE];
            #pragma unroll
            for (int e = 0; e < NE; e++) {
                gr0[e] = __ldg(&gw[(size_t)r * NE + e]);
                gr1[e] = __ldg(&gw[(size_t)(r + 8) * NE + e]);
            }
            #pragma unroll
            for (int ni = 0; ni < 4; ni++) {
                int c = n0 + wn * 32 + ni * 8 + t4 * 2;
                float v0 = acc[mi][ni][0], v1 = acc[mi][ni][1];
                float v2 = acc[mi][ni][2], v3 = acc[mi][ni][3];
                #pragma unroll
                for (int e = 0; e < NE; e++) {
                    float b2c0 = __ldg(&bias[e * NC + c]);
                    float b2c1 = __ldg(&bias[e * NC + c + 1]);
                    v0 = fmaf(gr0[e], b2c0, v0);
                    v1 = fmaf(gr0[e], b2c1, v1);
                    v2 = fmaf(gr1[e], b2c0, v2);
                    v3 = fmaf(gr1[e], b2c1, v3);
                }
                *(float2*)(outp + (size_t)r * NC + c)       = make_float2(v0, v1);
                *(float2*)(outp + (size_t)(r + 8) * NC + c) = make_float2(v2, v3);
            }
        }
    }
}

// ---------------- host ------------------------------------------------------
typedef CUresult (*EncFn)(CUtensorMap*, CUtensorMapDataType, cuuint32_t, void*,
                          const cuuint64_t*, const cuuint64_t*, const cuuint32_t*,
                          const cuuint32_t*, CUtensorMapInterleave, CUtensorMapSwizzle,
                          CUtensorMapL2promotion, CUtensorMapFloatOOBfill);

static void make2d(EncFn enc, CUtensorMap* m, void* ptr,
                   uint64_t d0, uint64_t d1, uint32_t b0, uint32_t b1) {
    cuuint64_t dims[2] = {d0, d1};
    cuuint64_t strides[1] = {d0 * 4};
    cuuint32_t box[2] = {b0, b1};
    cuuint32_t es[2] = {1, 1};
    enc(m, CU_TENSOR_MAP_DATA_TYPE_FLOAT32, 2, ptr, dims, strides, box, es,
        CU_TENSOR_MAP_INTERLEAVE_NONE, CU_TENSOR_MAP_SWIZZLE_128B,
        CU_TENSOR_MAP_L2_PROMOTION_L2_128B, CU_TENSOR_MAP_FLOAT_OOB_FILL_NONE);
}

extern "C" void kernel_launch(void* const* d_in, const int* in_sizes, int n_in,
                              void* d_out, int out_size) {
    const float* x  = (const float*)d_in[0];
    const float* gW = (const float*)d_in[1];
    const float* gb = (const float*)d_in[2];
    const float* W1 = (const float*)d_in[3];
    const float* b1 = (const float*)d_in[4];
    const float* W2 = (const float*)d_in[5];
    const float* b2 = (const float*)d_in[6];
    float* out   = (float*)d_out;
    float* gwbuf = out + (size_t)NB * NC;   // gw region of the output tuple

    void *p_xr, *p_w1, *p_w2, *p_h;
    cudaGetSymbolAddress(&p_xr, g_xr);
    cudaGetSymbolAddress(&p_w1, g_w1r);
    cudaGetSymbolAddress(&p_w2, g_w2r);
    cudaGetSymbolAddress(&p_h,  g_h);

    void* sym = nullptr;
    cudaDriverEntryPointQueryResult qr;
    cudaGetDriverEntryPointByVersion("cuTensorMapEncodeTiled", &sym, 12000,
                                     cudaEnableDefault, &qr);
    EncFn enc = (EncFn)sym;

    CUtensorMap mA1, mB1, mA2, mB2;
    make2d(enc, &mA1, p_xr, ND,  NB,  TK, TM);
    make2d(enc, &mB1, p_w1, ND,  NEH, TK, TN);
    make2d(enc, &mA2, p_h,  NEH, NB,  TK, TM);
    make2d(enc, &mB2, p_w2, NEH, NC,  TK, TN);

    cudaFuncSetAttribute(k_gemm<0>, cudaFuncAttributeMaxDynamicSharedMemorySize, SMEM_TOTAL);
    cudaFuncSetAttribute(k_gemm<1>, cudaFuncAttributeMaxDynamicSharedMemorySize, SMEM_TOTAL);

    k_rnd<<<4096, 256>>>((const float4*)x,  (float4*)p_xr, NB * ND / 4);
    k_rnd<<<4096, 256>>>((const float4*)W1, (float4*)p_w1, (int)((size_t)NEH * ND / 4));
    k_w2perm<<<(NC * NEH / 4 + 255) / 256, 256>>>(W2, (float*)p_w2);
    k_gate<<<NB / 8, 256>>>(x, gW, gb, gwbuf);

    k_gemm<0><<<dim3(NEH / TN, NB / TM), 256, SMEM_TOTAL>>>(
        mA1, mB1, b1, gwbuf, (float*)p_h, ND / TK);
    k_gemm<1><<<dim3(NC / TN, NB / TM), 256, SMEM_TOTAL>>>(
        mA2, mB2, b2, gwbuf, out, NEH / TK);
}

// round 6
// speedup vs baseline: 1.7463x; 1.7463x over previous
#include <cuda_runtime.h>
#include <cuda.h>
#include <cstdint>
#include <math.h>

// ---------------- problem dims ----------------
#define NB 16384
#define ND 2048
#define NH 2048
#define NE 6
#define NC 1024
#define NEH 12288       // E*H
// ---------------- tiling ----------------------
#define TM 128
#define TN 128
#define TK 32                      // k floats per stage = 128 bytes
#define STAGES 4
#define A_BYTES (TM*TK*4)          // 16384
#define B_BYTES (TN*TK*4)          // 16384
#define STAGE_BYTES (A_BYTES + B_BYTES)     // 32768
#define DATA_OFF 1024
#define SMEM_TOTAL (DATA_OFF + STAGES*STAGE_BYTES)   // 132096
#define KITERS 64                  // both GEMMs: 2048/32

// ---------------- scratch (device globals; no allocation) -----------------
__device__ float g_xr [(size_t)NB * ND];      // x rounded to tf32
__device__ float g_w1r[(size_t)NEH * ND];     // W1 rounded, [E*H, D] K-major
__device__ float g_w2r[(size_t)NE * NC * NH]; // W2 rounded, native [E,C,H] K-major
__device__ float g_h  [(size_t)NE * NB * NH]; // compact: gw-scaled gelu(xW1+b1)
__device__ float g_o  [(size_t)NE * NB * NC]; // compact expert outputs
__device__ int   g_rows[NE * NB];             // per-expert compacted row lists
__device__ int   g_cnt [NE];
__device__ int   g_idx [NB * 3];              // per row: (e<<14)|i  x3

// ---------------- ptx helpers ----------------------------------------------
__device__ __forceinline__ uint32_t smem_u32(const void* p) {
    uint32_t a;
    asm("{ .reg .u64 t; cvta.to.shared.u64 t, %1; cvt.u32.u64 %0, t; }"
        : "=r"(a) : "l"(p));
    return a;
}
__device__ __forceinline__ float rna_tf32(float f) {
    uint32_t u; asm("cvt.rna.tf32.f32 %0, %1;" : "=r"(u) : "f"(f));
    return __uint_as_float(u);
}
__device__ __forceinline__ uint32_t lds32(uint32_t addr) {
    uint32_t v; asm("ld.shared.b32 %0, [%1];" : "=r"(v) : "r"(addr));
    return v;
}

#define MBARRIER_INIT(addr, count) \
    asm volatile("mbarrier.init.shared.b64 [%0], %1;" \
        :: "r"((uint32_t)(addr)), "r"((uint32_t)(count)) : "memory")
#define MBARRIER_EXPECT_TX(addr, bytes) \
    asm volatile("mbarrier.arrive.expect_tx.shared.b64 _, [%0], %1;" \
        :: "r"((uint32_t)(addr)), "r"((uint32_t)(bytes)) : "memory")
#define MBARRIER_ARRIVE(addr) \
    asm volatile("mbarrier.arrive.shared.b64 _, [%0];" \
        :: "r"((uint32_t)(addr)) : "memory")

#define MBARRIER_WAIT_PARITY(mbar_smem_addr, phase_parity) do { \
    uint32_t _mbar = (uint32_t)(mbar_smem_addr); \
    uint32_t _parity = (uint32_t)(phase_parity); \
    uint32_t _done; \
    asm volatile("{\n\t.reg .pred p;\n\t" \
        "mbarrier.try_wait.parity.acquire.cta.shared::cta.b64 p, [%1], %2;\n\t" \
        "selp.b32 %0, 1, 0, p;\n\t}" \
        : "=r"(_done) : "r"(_mbar), "r"(_parity) : "memory"); \
    if (!_done) { \
        asm volatile("{\n\t.reg .pred P1;\n\t" \
            "WAIT_LOOP_%=:\n\t" \
            "mbarrier.try_wait.parity.acquire.cta.shared::cta.b64 P1, [%0], %1, 0x989680;\n\t" \
            "@P1 bra.uni WAIT_DONE_%=;\n\t" \
            "bra.uni WAIT_LOOP_%=;\n\t" \
            "WAIT_DONE_%=:\n\t}" \
            :: "r"(_mbar), "r"(_parity) : "memory"); \
    } \
} while (0)

#define MBARRIER_WAIT_PARITY_RELAXED(mbar_smem_addr, phase_parity) do { \
    uint32_t _mbar = (uint32_t)(mbar_smem_addr); \
    uint32_t _parity = (uint32_t)(phase_parity); \
    uint32_t _done; \
    asm volatile("{\n\t.reg .pred p;\n\t" \
        "mbarrier.try_wait.parity.relaxed.cta.shared::cta.b64 p, [%1], %2, 0x989680;\n\t" \
        "selp.b32 %0, 1, 0, p;\n\t}" \
        : "=r"(_done) : "r"(_mbar), "r"(_parity) : "memory"); \
    if (!_done) { \
        asm volatile("{\n\t.reg .pred P1;\n\t" \
            "WAIT_LOOP_%=:\n\t" \
            "mbarrier.try_wait.parity.relaxed.cta.shared::cta.b64 P1, [%0], %1, 0x989680;\n\t" \
            "@P1 bra.uni WAIT_DONE_%=;\n\t" \
            "bra.uni WAIT_LOOP_%=;\n\t" \
            "WAIT_DONE_%=:\n\t}" \
            :: "r"(_mbar), "r"(_parity) : "memory"); \
    } \
} while (0)

#define TMA2D(smem_addr, map_ptr, cx, cy, mbar) \
    asm volatile("cp.async.bulk.tensor.2d.shared::cta.global.tile.mbarrier::complete_tx::bytes " \
        "[%0], [%1, {%2, %3}], [%4];" \
        :: "r"((uint32_t)(smem_addr)), "l"(map_ptr), "r"((int)(cx)), "r"((int)(cy)), \
           "r"((uint32_t)(mbar)) : "memory")

#define CPASYNC16(dst, src) \
    asm volatile("cp.async.cg.shared.global [%0], [%1], 16;" \
        :: "r"((uint32_t)(dst)), "l"(src) : "memory")
#define CPCOMMIT() asm volatile("cp.async.commit_group;" ::: "memory")
#define CPWAIT2()  asm volatile("cp.async.wait_group 2;" ::: "memory")

// m16n8k8 tf32 HMMA, D += A*B
__device__ __forceinline__ void mma_tf32(float* d, const uint32_t* a, const uint32_t* b) {
    asm volatile("mma.sync.aligned.m16n8k8.row.col.f32.tf32.tf32.f32 "
        "{%0,%1,%2,%3}, {%4,%5,%6,%7}, {%8,%9}, {%0,%1,%2,%3};"
        : "+f"(d[0]), "+f"(d[1]), "+f"(d[2]), "+f"(d[3])
        : "r"(a[0]), "r"(a[1]), "r"(a[2]), "r"(a[3]), "r"(b[0]), "r"(b[1]));
}

__device__ __forceinline__ float gelu_exact(float x) {
    return 0.5f * x * (1.f + erff(x * 0.70710678118654752f));
}

// shared compute body: one TK-chunk of MMAs on stage buffers
__device__ __forceinline__ void compute_chunk(uint32_t aB, uint32_t bB,
                                              int wm, int wn, int g, int t4,
                                              float acc[4][4][4]) {
    #pragma unroll
    for (int kk = 0; kk < 4; kk++) {
        uint32_t a[4][4], b[4][2];
        #pragma unroll
        for (int mi = 0; mi < 4; mi++) {
            int r0 = wm * 64 + mi * 16 + g;
            uint32_t sw = (uint32_t)((r0 & 7) << 4);
            uint32_t c0 = (uint32_t)(kk * 32 + t4 * 4);
            a[mi][0] = lds32(aB + r0 * 128       + (c0        ^ sw));
            a[mi][1] = lds32(aB + (r0 + 8) * 128 + (c0        ^ sw));
            a[mi][2] = lds32(aB + r0 * 128       + ((c0 + 16) ^ sw));
            a[mi][3] = lds32(aB + (r0 + 8) * 128 + ((c0 + 16) ^ sw));
        }
        #pragma unroll
        for (int ni = 0; ni < 4; ni++) {
            int n = wn * 32 + ni * 8 + g;
            uint32_t sw = (uint32_t)((n & 7) << 4);
            uint32_t k0 = (uint32_t)(kk * 32 + t4 * 4);
            b[ni][0] = lds32(bB + n * 128 + (k0        ^ sw));
            b[ni][1] = lds32(bB + n * 128 + ((k0 + 16) ^ sw));
        }
        #pragma unroll
        for (int mi = 0; mi < 4; mi++)
            #pragma unroll
            for (int ni = 0; ni < 4; ni++)
                mma_tf32(acc[mi][ni], a[mi], b[ni]);
    }
}

// ---------------- small kernels ---------------------------------------------
__global__ void k_zero() {
    int i = blockIdx.x * blockDim.x + threadIdx.x;
    if (i < NE) g_cnt[i] = 0;
    if (i < NE * NB) g_rows[i] = 0;
}

__global__ void k_rnd(const float4* __restrict__ in, float4* __restrict__ out, int n4) {
    int i = blockIdx.x * blockDim.x + threadIdx.x;
    int stride = gridDim.x * blockDim.x;
    for (; i < n4; i += stride) {
        float4 v = in[i];
        v.x = rna_tf32(v.x); v.y = rna_tf32(v.y);
        v.z = rna_tf32(v.z); v.w = rna_tf32(v.w);
        out[i] = v;
    }
}

// gate: fp32 logits + top-3 softmax + per-expert compaction
__global__ void k_gate(const float* __restrict__ x, const float* __restrict__ gW,
                       const float* __restrict__ gb, float* __restrict__ gwout) {
    int row = blockIdx.x * 8 + (threadIdx.x >> 5);
    int lane = threadIdx.x & 31;
    const float* xr = x + (size_t)row * ND;
    float acc[NE];
    #pragma unroll
    for (int e = 0; e < NE; e++) acc[e] = 0.f;
    for (int d = lane * 4; d < ND; d += 128) {
        float4 xv = *(const float4*)(xr + d);
        #pragma unroll
        for (int e = 0; e < NE; e++) {
            float4 wv = *(const float4*)(gW + (size_t)e * ND + d);
            acc[e] += xv.x * wv.x + xv.y * wv.y + xv.z * wv.z + xv.w * wv.w;
        }
    }
    #pragma unroll
    for (int e = 0; e < NE; e++)
        #pragma unroll
        for (int o = 16; o > 0; o >>= 1)
            acc[e] += __shfl_xor_sync(0xFFFFFFFF, acc[e], o);
    float l[NE];
    #pragma unroll
    for (int e = 0; e < NE; e++) l[e] = acc[e] + gb[e];
    bool used[NE] = {false, false, false, false, false, false};
    float mx = -3.4e38f;
    for (int t = 0; t < 3; t++) {
        float best = -3.4e38f; int bi = 0;
        #pragma unroll
        for (int e = 0; e < NE; e++)
            if (!used[e] && l[e] > best) { best = l[e]; bi = e; }
        used[bi] = true;
        if (t == 0) mx = best;
    }
    float s = 0.f;
    #pragma unroll
    for (int e = 0; e < NE; e++) if (used[e]) s += expf(l[e] - mx);
    float inv = 1.f / s;
    if (lane < NE)
        gwout[(size_t)row * NE + lane] = used[lane] ? expf(l[lane] - mx) * inv : 0.f;
    if (lane == 0) {
        int t = 0;
        #pragma unroll
        for (int e = 0; e < NE; e++)
            if (used[e]) {
                int i = atomicAdd(&g_cnt[e], 1);
                g_rows[e * NB + i] = row;
                g_idx[row * 3 + t] = (e << 14) | i;
                t++;
            }
    }
}

// ---------------- GEMM1: gathered-A (cp.async) x TMA-B ----------------------
// per expert e: h_c[e][i][:] = rna( gelu( x[rows[e][i]] @ W1[e]^T + b1[e] ) * gw )
__global__ void __launch_bounds__(256, 1) k_gemm1(
    const __grid_constant__ CUtensorMap bmap,
    const float* __restrict__ xr,
    const float* __restrict__ b1,
    const float* __restrict__ gw,
    float* __restrict__ hout)
{
    const int e  = blockIdx.z;
    const int m0 = blockIdx.y * TM;
    const int n0 = blockIdx.x * TN;          // within H
    if (m0 >= g_cnt[e]) return;

    extern __shared__ __align__(1024) char smem[];
    const uint32_t sb = smem_u32(smem);
    const int tid  = threadIdx.x;
    const int lane = tid & 31;
    const int wid  = tid >> 5;
    const int wm = wid >> 2, wn = wid & 3;
    const int g = lane >> 2, t4 = lane & 3;
    const uint32_t FULL0 = sb;

    // per-thread A-gather plan: 4 x 16B chunks, fixed (row, chunk) per thread
    const float* srcp[4];
    uint32_t dsto[4];
    #pragma unroll
    for (int q = 0; q < 4; q++) {
        int cid = tid + 256 * q;
        int ar = cid >> 3, j = cid & 7;
        int grow = g_rows[e * NB + m0 + ar];
        srcp[q] = xr + (size_t)grow * ND + j * 4;
        dsto[q] = (uint32_t)(ar * 128 + ((j * 16) ^ ((ar & 7) << 4)));
    }

    if (tid == 0)
        #pragma unroll
        for (int s = 0; s < STAGES; s++) MBARRIER_INIT(FULL0 + s * 8, 1);
    __syncthreads();

    #define ISSUE_A(slot, kt) do { \
        uint32_t base = sb + DATA_OFF + (slot) * STAGE_BYTES; \
        _Pragma("unroll") \
        for (int q = 0; q < 4; q++) CPASYNC16(base + dsto[q], srcp[q] + (kt) * TK); \
    } while (0)

    // prologue: 3 stages in flight
    #pragma unroll
    for (int kt = 0; kt < STAGES - 1; kt++) {
        ISSUE_A(kt, kt);
        CPCOMMIT();
        if (tid == 0) {
            uint32_t fb = FULL0 + kt * 8;
            MBARRIER_EXPECT_TX(fb, B_BYTES);
            TMA2D(sb + DATA_OFF + kt * STAGE_BYTES + A_BYTES, &bmap,
                  kt * TK, e * NH + n0, fb);
        }
    }

    float acc[4][4][4];
    #pragma unroll
    for (int mi = 0; mi < 4; mi++)
        #pragma unroll
        for (int ni = 0; ni < 4; ni++)
            #pragma unroll
            for (int q = 0; q < 4; q++) acc[mi][ni][q] = 0.f;

    int sc = 0, pc = 0;
    for (int kt = 0; kt < KITERS; kt++) {
        CPWAIT2();                                 // our A chunks for kt done
        MBARRIER_WAIT_PARITY(FULL0 + sc * 8, pc);  // B tile for kt done
        __syncthreads();                           // cross-thread A visibility + reuse fence
        if (kt + STAGES - 1 < KITERS) {
            int sl = (sc + STAGES - 1) & (STAGES - 1);
            ISSUE_A(sl, kt + STAGES - 1);
            CPCOMMIT();
            if (tid == 0) {
                uint32_t fb = FULL0 + sl * 8;
                MBARRIER_EXPECT_TX(fb, B_BYTES);
                TMA2D(sb + DATA_OFF + sl * STAGE_BYTES + A_BYTES, &bmap,
                      (kt + STAGES - 1) * TK, e * NH + n0, fb);
            }
        } else {
            CPCOMMIT();                            // keep group count uniform
        }
        uint32_t aB = sb + DATA_OFF + sc * STAGE_BYTES;
        compute_chunk(aB, aB + A_BYTES, wm, wn, g, t4, acc);
        if (++sc == STAGES) { sc = 0; pc ^= 1; }
    }
    #undef ISSUE_A

    // epilogue: +b1, gelu, *gw, rna -> compact h
    #pragma unroll
    for (int mi = 0; mi < 4; mi++) {
        int i = m0 + wm * 64 + mi * 16 + g;
        int gb0 = g_rows[e * NB + i];
        int gb1 = g_rows[e * NB + i + 8];
        float gw0 = __ldg(&gw[(size_t)gb0 * NE + e]);
        float gw1 = __ldg(&gw[(size_t)gb1 * NE + e]);
        #pragma unroll
        for (int ni = 0; ni < 4; ni++) {
            int c = n0 + wn * 32 + ni * 8 + t4 * 2;
            float bb0 = __ldg(&b1[e * NH + c]);
            float bb1 = __ldg(&b1[e * NH + c + 1]);
            float v0 = rna_tf32(gelu_exact(acc[mi][ni][0] + bb0) * gw0);
            float v1 = rna_tf32(gelu_exact(acc[mi][ni][1] + bb1) * gw0);
            float v2 = rna_tf32(gelu_exact(acc[mi][ni][2] + bb0) * gw1);
            float v3 = rna_tf32(gelu_exact(acc[mi][ni][3] + bb1) * gw1);
            *(float2*)(hout + ((size_t)e * NB + i) * NH + c)     = make_float2(v0, v1);
            *(float2*)(hout + ((size_t)e * NB + i + 8) * NH + c) = make_float2(v2, v3);
        }
    }
}

// ---------------- GEMM2: TMA x TMA, compact rows, bare store ----------------
__global__ void __launch_bounds__(256, 1) k_gemm2(
    const __grid_constant__ CUtensorMap amap,
    const __grid_constant__ CUtensorMap bmap,
    float* __restrict__ outp)
{
    const int e  = blockIdx.z;
    const int m0 = blockIdx.y * TM;
    const int n0 = blockIdx.x * TN;
    if (m0 >= g_cnt[e]) return;

    extern __shared__ __align__(1024) char smem[];
    const uint32_t sb = smem_u32(smem);
    const int tid  = threadIdx.x;
    const int lane = tid & 31;
    const int wid  = tid >> 5;
    const int wm = wid >> 2, wn = wid & 3;
    const int g = lane >> 2, t4 = lane & 3;
    const uint32_t FULL0  = sb;
    const uint32_t EMPTY0 = sb + 64;

    if (tid == 0) {
        #pragma unroll
        for (int s = 0; s < STAGES; s++) {
            MBARRIER_INIT(FULL0  + s * 8, 1);
            MBARRIER_INIT(EMPTY0 + s * 8, 8);
        }
    }
    __syncthreads();

    float acc[4][4][4];
    #pragma unroll
    for (int mi = 0; mi < 4; mi++)
        #pragma unroll
        for (int ni = 0; ni < 4; ni++)
            #pragma unroll
            for (int q = 0; q < 4; q++) acc[mi][ni][q] = 0.f;

    int se = 0, pe = 1;
    #define ISSUE2(i) do { \
        MBARRIER_WAIT_PARITY_RELAXED(EMPTY0 + se * 8, pe); \
        uint32_t fb = FULL0 + se * 8; \
        MBARRIER_EXPECT_TX(fb, STAGE_BYTES); \
        uint32_t dst = sb + DATA_OFF + se * STAGE_BYTES; \
        TMA2D(dst,           &amap, (i) * TK, e * NB + m0, fb); \
        TMA2D(dst + A_BYTES, &bmap, (i) * TK, e * NC + n0, fb); \
        if (++se == STAGES) { se = 0; pe ^= 1; } \
    } while (0)

    if (tid == 0)
        for (int i = 0; i < STAGES - 1; i++) ISSUE2(i);

    int sc = 0, pc = 0;
    for (int kt = 0; kt < KITERS; kt++) {
        MBARRIER_WAIT_PARITY(FULL0 + sc * 8, pc);
        if (tid == 0 && kt + STAGES - 1 < KITERS) ISSUE2(kt + STAGES - 1);
        uint32_t aB = sb + DATA_OFF + sc * STAGE_BYTES;
        compute_chunk(aB, aB + A_BYTES, wm, wn, g, t4, acc);
        if (lane == 0) MBARRIER_ARRIVE(EMPTY0 + sc * 8);
        if (++sc == STAGES) { sc = 0; pc ^= 1; }
    }
    #undef ISSUE2

    #pragma unroll
    for (int mi = 0; mi < 4; mi++) {
        int i = m0 + wm * 64 + mi * 16 + g;
        #pragma unroll
        for (int ni = 0; ni < 4; ni++) {
            int c = n0 + wn * 32 + ni * 8 + t4 * 2;
            *(float2*)(outp + ((size_t)e * NB + i) * NC + c) =
                make_float2(acc[mi][ni][0], acc[mi][ni][1]);
            *(float2*)(outp + ((size_t)e * NB + i + 8) * NC + c) =
                make_float2(acc[mi][ni][2], acc[mi][ni][3]);
        }
    }
}

// ---------------- combine: gather top-3 expert outputs + bias ---------------
__global__ void k_comb(const float* __restrict__ gw, const float* __restrict__ b2,
                       float* __restrict__ out) {
    int b = blockIdx.x;
    int t = threadIdx.x;                       // 256 threads x float4 = 1024 cols
    const float4* go4 = (const float4*)g_o;
    const float4* b24 = (const float4*)b2;
    float4 a = make_float4(0.f, 0.f, 0.f, 0.f);
    #pragma unroll
    for (int tt = 0; tt < 3; tt++) {
        int v = g_idx[b * 3 + tt];
        int e = v >> 14, i = v & 16383;
        float4 s = go4[(((size_t)e * NB + i) * NC >> 2) + t];
        float w = __ldg(&gw[(size_t)b * NE + e]);
        float4 bb = b24[((size_t)e * NC >> 2) + t];
        a.x += s.x + w * bb.x;
        a.y += s.y + w * bb.y;
        a.z += s.z + w * bb.z;
        a.w += s.w + w * bb.w;
    }
    ((float4*)out)[(size_t)b * (NC / 4) + t] = a;
}

// ---------------- host ------------------------------------------------------
typedef CUresult (*EncFn)(CUtensorMap*, CUtensorMapDataType, cuuint32_t, void*,
                          const cuuint64_t*, const cuuint64_t*, const cuuint32_t*,
                          const cuuint32_t*, CUtensorMapInterleave, CUtensorMapSwizzle,
                          CUtensorMapL2promotion, CUtensorMapFloatOOBfill);

static void make2d(EncFn enc, CUtensorMap* m, void* ptr,
                   uint64_t d0, uint64_t d1, uint32_t b0, uint32_t b1) {
    cuuint64_t dims[2] = {d0, d1};
    cuuint64_t strides[1] = {d0 * 4};
    cuuint32_t box[2] = {b0, b1};
    cuuint32_t es[2] = {1, 1};
    enc(m, CU_TENSOR_MAP_DATA_TYPE_FLOAT32, 2, ptr, dims, strides, box, es,
        CU_TENSOR_MAP_INTERLEAVE_NONE, CU_TENSOR_MAP_SWIZZLE_128B,
        CU_TENSOR_MAP_L2_PROMOTION_L2_128B, CU_TENSOR_MAP_FLOAT_OOB_FILL_NONE);
}

extern "C" void kernel_launch(void* const* d_in, const int* in_sizes, int n_in,
                              void* d_out, int out_size) {
    const float* x  = (const float*)d_in[0];
    const float* gW = (const float*)d_in[1];
    const float* gb = (const float*)d_in[2];
    const float* W1 = (const float*)d_in[3];
    const float* b1 = (const float*)d_in[4];
    const float* W2 = (const float*)d_in[5];
    const float* b2 = (const float*)d_in[6];
    float* out   = (float*)d_out;
    float* gwbuf = out + (size_t)NB * NC;     // gw region of the output tuple

    void *p_xr, *p_w1, *p_w2, *p_h, *p_o;
    cudaGetSymbolAddress(&p_xr, g_xr);
    cudaGetSymbolAddress(&p_w1, g_w1r);
    cudaGetSymbolAddress(&p_w2, g_w2r);
    cudaGetSymbolAddress(&p_h,  g_h);
    cudaGetSymbolAddress(&p_o,  g_o);

    void* sym = nullptr;
    cudaDriverEntryPointQueryResult qr;
    cudaGetDriverEntryPointByVersion("cuTensorMapEncodeTiled", &sym, 12000,
                                     cudaEnableDefault, &qr);
    EncFn enc = (EncFn)sym;

    CUtensorMap mB1, mA2, mB2;
    make2d(enc, &mB1, p_w1, ND, NEH,             TK, TN);  // W1 [E*H, D]
    make2d(enc, &mA2, p_h,  NH, (uint64_t)NE*NB, TK, TM);  // h_c [E*NB, H]
    make2d(enc, &mB2, p_w2, NH, (uint64_t)NE*NC, TK, TN);  // W2 [E*C, H]

    cudaFuncSetAttribute(k_gemm1, cudaFuncAttributeMaxDynamicSharedMemorySize, SMEM_TOTAL);
    cudaFuncSetAttribute(k_gemm2, cudaFuncAttributeMaxDynamicSharedMemorySize, SMEM_TOTAL);

    k_zero<<<(NE * NB + 255) / 256, 256>>>();
    k_rnd<<<4096, 256>>>((const float4*)x,  (float4*)p_xr, NB * ND / 4);
    k_rnd<<<4096, 256>>>((const float4*)W1, (float4*)p_w1, (int)((size_t)NEH * ND / 4));
    k_rnd<<<4096, 256>>>((const float4*)W2, (float4*)p_w2, (int)((size_t)NE * NC * NH / 4));
    k_gate<<<NB / 8, 256>>>(x, gW, gb, gwbuf);

    k_gemm1<<<dim3(NH / TN, NB / TM, NE), 256, SMEM_TOTAL>>>(
        mB1, (const float*)p_xr, b1, gwbuf, (float*)p_h);
    k_gemm2<<<dim3(NC / TN, NB / TM, NE), 256, SMEM_TOTAL>>>(
        mA2, mB2, (float*)p_o);
    k_comb<<<NB, 256>>>(gwbuf, b2, out);
}

// round 7
// speedup vs baseline: 2.0904x; 1.1970x over previous
#include <cuda_runtime.h>
#include <cuda.h>
#include <cstdint>
#include <math.h>

// ---------------- problem dims ----------------
#define NB 16384
#define ND 2048
#define NH 2048
#define NE 6
#define NC 1024
#define NEH 12288       // E*H
// ---------------- tiling ----------------------
#define TM 128
#define TN 256
#define TK 32                      // k floats per stage = 128 bytes
#define STAGES 4
#define A_BYTES (TM*TK*4)          // 16384
#define B_BYTES (TN*TK*4)          // 32768
#define STAGE_BYTES (A_BYTES + B_BYTES)     // 49152
#define DATA_OFF 1024
#define SMEM_TOTAL (DATA_OFF + STAGES*STAGE_BYTES)   // 197632
#define KITERS 64                  // both GEMMs: 2048/32

// ---------------- scratch (device globals; no allocation) -----------------
__device__ float g_xg [(size_t)NE * NB * ND]; // gathered+rounded x per expert
__device__ float g_w1r[(size_t)NEH * ND];     // W1 rounded, [E*H, D] K-major
__device__ float g_w2r[(size_t)NE * NC * NH]; // W2 rounded, native [E,C,H] K-major
__device__ float g_h  [(size_t)NE * NB * NH]; // compact: gw-scaled gelu(xW1+b1)
__device__ float g_o  [(size_t)NE * NB * NC]; // compact expert outputs
__device__ int   g_rows[NE * NB];             // per-expert compacted row lists
__device__ int   g_cnt [NE];
__device__ int   g_idx [NB * 3];              // per row: (e<<14)|i  x3

// ---------------- ptx helpers ----------------------------------------------
__device__ __forceinline__ uint32_t smem_u32(const void* p) {
    uint32_t a;
    asm("{ .reg .u64 t; cvta.to.shared.u64 t, %1; cvt.u32.u64 %0, t; }"
        : "=r"(a) : "l"(p));
    return a;
}
__device__ __forceinline__ float rna_tf32(float f) {
    uint32_t u; asm("cvt.rna.tf32.f32 %0, %1;" : "=r"(u) : "f"(f));
    return __uint_as_float(u);
}
__device__ __forceinline__ uint32_t lds32(uint32_t addr) {
    uint32_t v; asm("ld.shared.b32 %0, [%1];" : "=r"(v) : "r"(addr));
    return v;
}

#define MBARRIER_INIT(addr, count) \
    asm volatile("mbarrier.init.shared.b64 [%0], %1;" \
        :: "r"((uint32_t)(addr)), "r"((uint32_t)(count)) : "memory")
#define MBARRIER_EXPECT_TX(addr, bytes) \
    asm volatile("mbarrier.arrive.expect_tx.shared.b64 _, [%0], %1;" \
        :: "r"((uint32_t)(addr)), "r"((uint32_t)(bytes)) : "memory")
#define MBARRIER_ARRIVE(addr) \
    asm volatile("mbarrier.arrive.shared.b64 _, [%0];" \
        :: "r"((uint32_t)(addr)) : "memory")

#define MBARRIER_WAIT_PARITY(mbar_smem_addr, phase_parity) do { \
    uint32_t _mbar = (uint32_t)(mbar_smem_addr); \
    uint32_t _parity = (uint32_t)(phase_parity); \
    uint32_t _done; \
    asm volatile("{\n\t.reg .pred p;\n\t" \
        "mbarrier.try_wait.parity.acquire.cta.shared::cta.b64 p, [%1], %2;\n\t" \
        "selp.b32 %0, 1, 0, p;\n\t}" \
        : "=r"(_done) : "r"(_mbar), "r"(_parity) : "memory"); \
    if (!_done) { \
        asm volatile("{\n\t.reg .pred P1;\n\t" \
            "WAIT_LOOP_%=:\n\t" \
            "mbarrier.try_wait.parity.acquire.cta.shared::cta.b64 P1, [%0], %1, 0x989680;\n\t" \
            "@P1 bra.uni WAIT_DONE_%=;\n\t" \
            "bra.uni WAIT_LOOP_%=;\n\t" \
            "WAIT_DONE_%=:\n\t}" \
            :: "r"(_mbar), "r"(_parity) : "memory"); \
    } \
} while (0)

#define MBARRIER_WAIT_PARITY_RELAXED(mbar_smem_addr, phase_parity) do { \
    uint32_t _mbar = (uint32_t)(mbar_smem_addr); \
    uint32_t _parity = (uint32_t)(phase_parity); \
    uint32_t _done; \
    asm volatile("{\n\t.reg .pred p;\n\t" \
        "mbarrier.try_wait.parity.relaxed.cta.shared::cta.b64 p, [%1], %2, 0x989680;\n\t" \
        "selp.b32 %0, 1, 0, p;\n\t}" \
        : "=r"(_done) : "r"(_mbar), "r"(_parity) : "memory"); \
    if (!_done) { \
        asm volatile("{\n\t.reg .pred P1;\n\t" \
            "WAIT_LOOP_%=:\n\t" \
            "mbarrier.try_wait.parity.relaxed.cta.shared::cta.b64 P1, [%0], %1, 0x989680;\n\t" \
            "@P1 bra.uni WAIT_DONE_%=;\n\t" \
            "bra.uni WAIT_LOOP_%=;\n\t" \
            "WAIT_DONE_%=:\n\t}" \
            :: "r"(_mbar), "r"(_parity) : "memory"); \
    } \
} while (0)

#define TMA2D(smem_addr, map_ptr, cx, cy, mbar) \
    asm volatile("cp.async.bulk.tensor.2d.shared::cta.global.tile.mbarrier::complete_tx::bytes " \
        "[%0], [%1, {%2, %3}], [%4];" \
        :: "r"((uint32_t)(smem_addr)), "l"(map_ptr), "r"((int)(cx)), "r"((int)(cy)), \
           "r"((uint32_t)(mbar)) : "memory")

// m16n8k8 tf32 HMMA, D += A*B
__device__ __forceinline__ void mma_tf32(float* d, const uint32_t* a, const uint32_t* b) {
    asm volatile("mma.sync.aligned.m16n8k8.row.col.f32.tf32.tf32.f32 "
        "{%0,%1,%2,%3}, {%4,%5,%6,%7}, {%8,%9}, {%0,%1,%2,%3};"
        : "+f"(d[0]), "+f"(d[1]), "+f"(d[2]), "+f"(d[3])
        : "r"(a[0]), "r"(a[1]), "r"(a[2]), "r"(a[3]), "r"(b[0]), "r"(b[1]));
}

__device__ __forceinline__ float gelu_exact(float x) {
    return 0.5f * x * (1.f + erff(x * 0.70710678118654752f));
}

// ---------------- small kernels ---------------------------------------------
__global__ void k_zero() {
    int i = blockIdx.x * blockDim.x + threadIdx.x;
    if (i < NE) g_cnt[i] = 0;
    if (i < NE * NB) g_rows[i] = 0;
}

__global__ void k_rnd(const float4* __restrict__ in, float4* __restrict__ out, int n4) {
    int i = blockIdx.x * blockDim.x + threadIdx.x;
    int stride = gridDim.x * blockDim.x;
    for (; i < n4; i += stride) {
        float4 v = in[i];
        v.x = rna_tf32(v.x); v.y = rna_tf32(v.y);
        v.z = rna_tf32(v.z); v.w = rna_tf32(v.w);
        out[i] = v;
    }
}

// gate: fp32 logits + top-3 softmax + per-expert compaction
__global__ void k_gate(const float* __restrict__ x, const float* __restrict__ gW,
                       const float* __restrict__ gb, float* __restrict__ gwout) {
    int row = blockIdx.x * 8 + (threadIdx.x >> 5);
    int lane = threadIdx.x & 31;
    const float* xr = x + (size_t)row * ND;
    float acc[NE];
    #pragma unroll
    for (int e = 0; e < NE; e++) acc[e] = 0.f;
    for (int d = lane * 4; d < ND; d += 128) {
        float4 xv = *(const float4*)(xr + d);
        #pragma unroll
        for (int e = 0; e < NE; e++) {
            float4 wv = *(const float4*)(gW + (size_t)e * ND + d);
            acc[e] += xv.x * wv.x + xv.y * wv.y + xv.z * wv.z + xv.w * wv.w;
        }
    }
    #pragma unroll
    for (int e = 0; e < NE; e++)
        #pragma unroll
        for (int o = 16; o > 0; o >>= 1)
            acc[e] += __shfl_xor_sync(0xFFFFFFFF, acc[e], o);
    float l[NE];
    #pragma unroll
    for (int e = 0; e < NE; e++) l[e] = acc[e] + gb[e];
    bool used[NE] = {false, false, false, false, false, false};
    float mx = -3.4e38f;
    for (int t = 0; t < 3; t++) {
        float best = -3.4e38f; int bi = 0;
        #pragma unroll
        for (int e = 0; e < NE; e++)
            if (!used[e] && l[e] > best) { best = l[e]; bi = e; }
        used[bi] = true;
        if (t == 0) mx = best;
    }
    float s = 0.f;
    #pragma unroll
    for (int e = 0; e < NE; e++) if (used[e]) s += expf(l[e] - mx);
    float inv = 1.f / s;
    if (lane < NE)
        gwout[(size_t)row * NE + lane] = used[lane] ? expf(l[lane] - mx) * inv : 0.f;
    if (lane == 0) {
        int t = 0;
        #pragma unroll
        for (int e = 0; e < NE; e++)
            if (used[e]) {
                int i = atomicAdd(&g_cnt[e], 1);
                g_rows[e * NB + i] = row;
                g_idx[row * 3 + t] = (e << 14) | i;
                t++;
            }
    }
}

// gather x rows per expert, fused with tf32 rounding -> g_xg[e][i][:]
__global__ void k_gather(const float* __restrict__ x) {
    const int e  = blockIdx.y;
    const int m0 = blockIdx.x * TM;
    if (m0 >= g_cnt[e]) return;
    const int t = threadIdx.x;            // 256 threads
    const int r = t >> 1;                 // rows handled per CTA: 128
    const int half = t & 1;               // 1024 floats each half
    int grow = g_rows[e * NB + m0 + r];
    const float4* src = (const float4*)(x + (size_t)grow * ND) + half * 256;
    float4* dst = (float4*)(g_xg + ((size_t)e * NB + m0 + r) * ND) + half * 256;
    #pragma unroll 8
    for (int j = 0; j < 256; j++) {
        float4 v = src[j];
        v.x = rna_tf32(v.x); v.y = rna_tf32(v.y);
        v.z = rna_tf32(v.z); v.w = rna_tf32(v.w);
        dst[j] = v;
    }
}

// ---------------- unified GEMM: TMA x TMA, 128x256 CTA, 64x64 warp tiles ----
// MODE 0: A=g_xg, B=W1r; epi: +b1, gelu, *gw, rna -> g_h
// MODE 1: A=g_h,  B=W2r; epi: bare store -> g_o
template <int MODE>
__global__ void __launch_bounds__(256, 1) k_gemm(
    const __grid_constant__ CUtensorMap amap,
    const __grid_constant__ CUtensorMap bmap,
    const float* __restrict__ bias,
    const float* __restrict__ gw,
    float* __restrict__ outp)
{
    const int e  = blockIdx.z;
    const int m0 = blockIdx.y * TM;
    const int n0 = blockIdx.x * TN;
    if (m0 >= g_cnt[e]) return;

    extern __shared__ __align__(1024) char smem[];
    const uint32_t sb = smem_u32(smem);
    const int tid  = threadIdx.x;
    const int lane = tid & 31;
    const int wid  = tid >> 5;
    const int wm = wid >> 2, wn = wid & 3;   // 2 x 4 warp grid, 64x64 tiles
    const int g = lane >> 2, t4 = lane & 3;
    const uint32_t FULL0  = sb;
    const uint32_t EMPTY0 = sb + 64;
    const int NB_DIM = (MODE == 0) ? NH : NC;   // B row-space per expert

    if (tid == 0) {
        #pragma unroll
        for (int s = 0; s < STAGES; s++) {
            MBARRIER_INIT(FULL0  + s * 8, 1);
            MBARRIER_INIT(EMPTY0 + s * 8, 8);
        }
    }
    __syncthreads();

    float acc[4][8][4];
    #pragma unroll
    for (int mi = 0; mi < 4; mi++)
        #pragma unroll
        for (int ni = 0; ni < 8; ni++)
            #pragma unroll
            for (int q = 0; q < 4; q++) acc[mi][ni][q] = 0.f;

    int se = 0, pe = 1;
    #define ISSUE(i) do { \
        MBARRIER_WAIT_PARITY_RELAXED(EMPTY0 + se * 8, pe); \
        uint32_t fb = FULL0 + se * 8; \
        MBARRIER_EXPECT_TX(fb, STAGE_BYTES); \
        uint32_t dst = sb + DATA_OFF + se * STAGE_BYTES; \
        TMA2D(dst,           &amap, (i) * TK, e * NB + m0, fb); \
        TMA2D(dst + A_BYTES, &bmap, (i) * TK, e * NB_DIM + n0, fb); \
        if (++se == STAGES) { se = 0; pe ^= 1; } \
    } while (0)

    if (tid == 0)
        for (int i = 0; i < STAGES - 1; i++) ISSUE(i);

    int sc = 0, pc = 0;
    for (int kt = 0; kt < KITERS; kt++) {
        MBARRIER_WAIT_PARITY(FULL0 + sc * 8, pc);
        if (tid == 0 && kt + STAGES - 1 < KITERS) ISSUE(kt + STAGES - 1);
        uint32_t aB = sb + DATA_OFF + sc * STAGE_BYTES;
        uint32_t bB = aB + A_BYTES;
        #pragma unroll
        for (int kk = 0; kk < 4; kk++) {
            uint32_t a[4][4], b[8][2];
            #pragma unroll
            for (int mi = 0; mi < 4; mi++) {
                int r0 = wm * 64 + mi * 16 + g;
                uint32_t sw = (uint32_t)((r0 & 7) << 4);
                uint32_t c0 = (uint32_t)(kk * 32 + t4 * 4);
                a[mi][0] = lds32(aB + r0 * 128       + (c0        ^ sw));
                a[mi][1] = lds32(aB + (r0 + 8) * 128 + (c0        ^ sw));
                a[mi][2] = lds32(aB + r0 * 128       + ((c0 + 16) ^ sw));
                a[mi][3] = lds32(aB + (r0 + 8) * 128 + ((c0 + 16) ^ sw));
            }
            #pragma unroll
            for (int ni = 0; ni < 8; ni++) {
                int n = wn * 64 + ni * 8 + g;
                uint32_t sw = (uint32_t)((n & 7) << 4);
                uint32_t k0 = (uint32_t)(kk * 32 + t4 * 4);
                b[ni][0] = lds32(bB + n * 128 + (k0        ^ sw));
                b[ni][1] = lds32(bB + n * 128 + ((k0 + 16) ^ sw));
            }
            #pragma unroll
            for (int mi = 0; mi < 4; mi++)
                #pragma unroll
                for (int ni = 0; ni < 8; ni++)
                    mma_tf32(acc[mi][ni], a[mi], b[ni]);
        }
        if (lane == 0) MBARRIER_ARRIVE(EMPTY0 + sc * 8);
        if (++sc == STAGES) { sc = 0; pc ^= 1; }
    }
    #undef ISSUE

    // ---------------- epilogue ----------------------------------------------
    if (MODE == 0) {
        #pragma unroll
        for (int mi = 0; mi < 4; mi++) {
            int i = m0 + wm * 64 + mi * 16 + g;
            int gb0 = g_rows[e * NB + i];
            int gb1 = g_rows[e * NB + i + 8];
            float gw0 = __ldg(&gw[(size_t)gb0 * NE + e]);
            float gw1 = __ldg(&gw[(size_t)gb1 * NE + e]);
            #pragma unroll
            for (int ni = 0; ni < 8; ni++) {
                int c = n0 + wn * 64 + ni * 8 + t4 * 2;
                float bb0 = __ldg(&bias[e * NH + c]);
                float bb1 = __ldg(&bias[e * NH + c + 1]);
                float v0 = rna_tf32(gelu_exact(acc[mi][ni][0] + bb0) * gw0);
                float v1 = rna_tf32(gelu_exact(acc[mi][ni][1] + bb1) * gw0);
                float v2 = rna_tf32(gelu_exact(acc[mi][ni][2] + bb0) * gw1);
                float v3 = rna_tf32(gelu_exact(acc[mi][ni][3] + bb1) * gw1);
                *(float2*)(outp + ((size_t)e * NB + i) * NH + c)     = make_float2(v0, v1);
                *(float2*)(outp + ((size_t)e * NB + i + 8) * NH + c) = make_float2(v2, v3);
            }
        }
    } else {
        #pragma unroll
        for (int mi = 0; mi < 4; mi++) {
            int i = m0 + wm * 64 + mi * 16 + g;
            #pragma unroll
            for (int ni = 0; ni < 8; ni++) {
                int c = n0 + wn * 64 + ni * 8 + t4 * 2;
                *(float2*)(outp + ((size_t)e * NB + i) * NC + c) =
                    make_float2(acc[mi][ni][0], acc[mi][ni][1]);
                *(float2*)(outp + ((size_t)e * NB + i + 8) * NC + c) =
                    make_float2(acc[mi][ni][2], acc[mi][ni][3]);
            }
        }
    }
}

// ---------------- combine: gather top-3 expert outputs + bias ---------------
__global__ void k_comb(const float* __restrict__ gw, const float* __restrict__ b2,
                       float* __restrict__ out) {
    int b = blockIdx.x;
    int t = threadIdx.x;
    const float4* go4 = (const float4*)g_o;
    const float4* b24 = (const float4*)b2;
    float4 a = make_float4(0.f, 0.f, 0.f, 0.f);
    #pragma unroll
    for (int tt = 0; tt < 3; tt++) {
        int v = g_idx[b * 3 + tt];
        int e = v >> 14, i = v & 16383;
        float4 s = go4[(((size_t)e * NB + i) * NC >> 2) + t];
        float w = __ldg(&gw[(size_t)b * NE + e]);
        float4 bb = b24[((size_t)e * NC >> 2) + t];
        a.x += s.x + w * bb.x;
        a.y += s.y + w * bb.y;
        a.z += s.z + w * bb.z;
        a.w += s.w + w * bb.w;
    }
    ((float4*)out)[(size_t)b * (NC / 4) + t] = a;
}

// ---------------- host ------------------------------------------------------
typedef CUresult (*EncFn)(CUtensorMap*, CUtensorMapDataType, cuuint32_t, void*,
                          const cuuint64_t*, const cuuint64_t*, const cuuint32_t*,
                          const cuuint32_t*, CUtensorMapInterleave, CUtensorMapSwizzle,
                          CUtensorMapL2promotion, CUtensorMapFloatOOBfill);

static void make2d(EncFn enc, CUtensorMap* m, void* ptr,
                   uint64_t d0, uint64_t d1, uint32_t b0, uint32_t b1) {
    cuuint64_t dims[2] = {d0, d1};
    cuuint64_t strides[1] = {d0 * 4};
    cuuint32_t box[2] = {b0, b1};
    cuuint32_t es[2] = {1, 1};
    enc(m, CU_TENSOR_MAP_DATA_TYPE_FLOAT32, 2, ptr, dims, strides, box, es,
        CU_TENSOR_MAP_INTERLEAVE_NONE, CU_TENSOR_MAP_SWIZZLE_128B,
        CU_TENSOR_MAP_L2_PROMOTION_L2_128B, CU_TENSOR_MAP_FLOAT_OOB_FILL_NONE);
}

extern "C" void kernel_launch(void* const* d_in, const int* in_sizes, int n_in,
                              void* d_out, int out_size) {
    const float* x  = (const float*)d_in[0];
    const float* gW = (const float*)d_in[1];
    const float* gb = (const float*)d_in[2];
    const float* W1 = (const float*)d_in[3];
    const float* b1 = (const float*)d_in[4];
    const float* W2 = (const float*)d_in[5];
    const float* b2 = (const float*)d_in[6];
    float* out   = (float*)d_out;
    float* gwbuf = out + (size_t)NB * NC;     // gw region of the output tuple

    void *p_xg, *p_w1, *p_w2, *p_h, *p_o;
    cudaGetSymbolAddress(&p_xg, g_xg);
    cudaGetSymbolAddress(&p_w1, g_w1r);
    cudaGetSymbolAddress(&p_w2, g_w2r);
    cudaGetSymbolAddress(&p_h,  g_h);
    cudaGetSymbolAddress(&p_o,  g_o);

    void* sym = nullptr;
    cudaDriverEntryPointQueryResult qr;
    cudaGetDriverEntryPointByVersion("cuTensorMapEncodeTiled", &sym, 12000,
                                     cudaEnableDefault, &qr);
    EncFn enc = (EncFn)sym;

    CUtensorMap mA1, mB1, mA2, mB2;
    make2d(enc, &mA1, p_xg, ND, (uint64_t)NE*NB, TK, TM);  // x gathered [E*NB, D]
    make2d(enc, &mB1, p_w1, ND, NEH,             TK, TN);  // W1 [E*H, D]
    make2d(enc, &mA2, p_h,  NH, (uint64_t)NE*NB, TK, TM);  // h_c [E*NB, H]
    make2d(enc, &mB2, p_w2, NH, (uint64_t)NE*NC, TK, TN);  // W2 [E*C, H]

    cudaFuncSetAttribute(k_gemm<0>, cudaFuncAttributeMaxDynamicSharedMemorySize, SMEM_TOTAL);
    cudaFuncSetAttribute(k_gemm<1>, cudaFuncAttributeMaxDynamicSharedMemorySize, SMEM_TOTAL);

    k_zero<<<(NE * NB + 255) / 256, 256>>>();
    k_rnd<<<4096, 256>>>((const float4*)W1, (float4*)p_w1, (int)((size_t)NEH * ND / 4));
    k_rnd<<<4096, 256>>>((const float4*)W2, (float4*)p_w2, (int)((size_t)NE * NC * NH / 4));
    k_gate<<<NB / 8, 256>>>(x, gW, gb, gwbuf);
    k_gather<<<dim3(NB / TM, NE), 256>>>(x);

    k_gemm<0><<<dim3(NH / TN, NB / TM, NE), 256, SMEM_TOTAL>>>(
        mA1, mB1, b1, gwbuf, (float*)p_h);
    k_gemm<1><<<dim3(NC / TN, NB / TM, NE), 256, SMEM_TOTAL>>>(
        mA2, mB2, b2, gwbuf, (float*)p_o);
    k_comb<<<NB, 256>>>(gwbuf, b2, out);
}

// round 8
// speedup vs baseline: 2.1677x; 1.0370x over previous
#include <cuda_runtime.h>
#include <cuda.h>
#include <cstdint>
#include <math.h>

// ---------------- problem dims ----------------
#define NB 16384
#define ND 2048
#define NH 2048
#define NE 6
#define NC 1024
#define NEH 12288       // E*H
// ---------------- tiling ----------------------
#define TM 128
#define TN 256
#define TK 32                      // k floats per stage = 128 bytes
#define STAGES 4
#define A_BYTES (TM*TK*4)          // 16384
#define B_BYTES (TN*TK*4)          // 32768
#define STAGE_BYTES (A_BYTES + B_BYTES)     // 49152
#define DATA_OFF 1024
#define SMEM_TOTAL (DATA_OFF + STAGES*STAGE_BYTES)   // 197632
#define KITERS 64                  // both GEMMs: 2048/32

// ---------------- scratch (device globals; no allocation) -----------------
__device__ float g_xg [(size_t)NE * NB * ND]; // gathered+rounded x per expert
__device__ float g_w1r[(size_t)NEH * ND];     // W1 rounded, [E*H, D] K-major
__device__ float g_w2r[(size_t)NE * NC * NH]; // W2 rounded, native [E,C,H] K-major
__device__ float g_h  [(size_t)NE * NB * NH]; // compact: gw-scaled gelu(xW1+b1)
__device__ float g_o  [(size_t)NE * NB * NC]; // compact expert outputs
__device__ int   g_rows[NE * NB];             // per-expert compacted row lists
__device__ int   g_cnt [NE];
__device__ int   g_idx [NB * 3];              // per row: (e<<14)|i  x3

// ---------------- ptx helpers ----------------------------------------------
__device__ __forceinline__ uint32_t smem_u32(const void* p) {
    uint32_t a;
    asm("{ .reg .u64 t; cvta.to.shared.u64 t, %1; cvt.u32.u64 %0, t; }"
        : "=r"(a) : "l"(p));
    return a;
}
__device__ __forceinline__ float rna_tf32(float f) {
    uint32_t u; asm("cvt.rna.tf32.f32 %0, %1;" : "=r"(u) : "f"(f));
    return __uint_as_float(u);
}

#define LDSM4(r0, r1, r2, r3, addr) \
    asm volatile("ldmatrix.sync.aligned.m8n8.x4.shared.b16 {%0,%1,%2,%3}, [%4];" \
        : "=r"(r0), "=r"(r1), "=r"(r2), "=r"(r3) : "r"((uint32_t)(addr)))

#define MBARRIER_INIT(addr, count) \
    asm volatile("mbarrier.init.shared.b64 [%0], %1;" \
        :: "r"((uint32_t)(addr)), "r"((uint32_t)(count)) : "memory")
#define MBARRIER_EXPECT_TX(addr, bytes) \
    asm volatile("mbarrier.arrive.expect_tx.shared.b64 _, [%0], %1;" \
        :: "r"((uint32_t)(addr)), "r"((uint32_t)(bytes)) : "memory")
#define MBARRIER_ARRIVE(addr) \
    asm volatile("mbarrier.arrive.shared.b64 _, [%0];" \
        :: "r"((uint32_t)(addr)) : "memory")

#define MBARRIER_WAIT_PARITY(mbar_smem_addr, phase_parity) do { \
    uint32_t _mbar = (uint32_t)(mbar_smem_addr); \
    uint32_t _parity = (uint32_t)(phase_parity); \
    uint32_t _done; \
    asm volatile("{\n\t.reg .pred p;\n\t" \
        "mbarrier.try_wait.parity.acquire.cta.shared::cta.b64 p, [%1], %2;\n\t" \
        "selp.b32 %0, 1, 0, p;\n\t}" \
        : "=r"(_done) : "r"(_mbar), "r"(_parity) : "memory"); \
    if (!_done) { \
        asm volatile("{\n\t.reg .pred P1;\n\t" \
            "WAIT_LOOP_%=:\n\t" \
            "mbarrier.try_wait.parity.acquire.cta.shared::cta.b64 P1, [%0], %1, 0x989680;\n\t" \
            "@P1 bra.uni WAIT_DONE_%=;\n\t" \
            "bra.uni WAIT_LOOP_%=;\n\t" \
            "WAIT_DONE_%=:\n\t}" \
            :: "r"(_mbar), "r"(_parity) : "memory"); \
    } \
} while (0)

#define MBARRIER_WAIT_PARITY_RELAXED(mbar_smem_addr, phase_parity) do { \
    uint32_t _mbar = (uint32_t)(mbar_smem_addr); \
    uint32_t _parity = (uint32_t)(phase_parity); \
    uint32_t _done; \
    asm volatile("{\n\t.reg .pred p;\n\t" \
        "mbarrier.try_wait.parity.relaxed.cta.shared::cta.b64 p, [%1], %2, 0x989680;\n\t" \
        "selp.b32 %0, 1, 0, p;\n\t}" \
        : "=r"(_done) : "r"(_mbar), "r"(_parity) : "memory"); \
    if (!_done) { \
        asm volatile("{\n\t.reg .pred P1;\n\t" \
            "WAIT_LOOP_%=:\n\t" \
            "mbarrier.try_wait.parity.relaxed.cta.shared::cta.b64 P1, [%0], %1, 0x989680;\n\t" \
            "@P1 bra.uni WAIT_DONE_%=;\n\t" \
            "bra.uni WAIT_LOOP_%=;\n\t" \
            "WAIT_DONE_%=:\n\t}" \
            :: "r"(_mbar), "r"(_parity) : "memory"); \
    } \
} while (0)

#define TMA2D(smem_addr, map_ptr, cx, cy, mbar) \
    asm volatile("cp.async.bulk.tensor.2d.shared::cta.global.tile.mbarrier::complete_tx::bytes " \
        "[%0], [%1, {%2, %3}], [%4];" \
        :: "r"((uint32_t)(smem_addr)), "l"(map_ptr), "r"((int)(cx)), "r"((int)(cy)), \
           "r"((uint32_t)(mbar)) : "memory")

// m16n8k8 tf32 HMMA, D += A*B
__device__ __forceinline__ void mma_tf32(float* d, const uint32_t* a, const uint32_t* b) {
    asm volatile("mma.sync.aligned.m16n8k8.row.col.f32.tf32.tf32.f32 "
        "{%0,%1,%2,%3}, {%4,%5,%6,%7}, {%8,%9}, {%0,%1,%2,%3};"
        : "+f"(d[0]), "+f"(d[1]), "+f"(d[2]), "+f"(d[3])
        : "r"(a[0]), "r"(a[1]), "r"(a[2]), "r"(a[3]), "r"(b[0]), "r"(b[1]));
}

__device__ __forceinline__ float gelu_exact(float x) {
    return 0.5f * x * (1.f + erff(x * 0.70710678118654752f));
}

// ---------------- small kernels ---------------------------------------------
__global__ void k_zero() {
    int i = blockIdx.x * blockDim.x + threadIdx.x;
    if (i < NE) g_cnt[i] = 0;
    if (i < NE * NB) g_rows[i] = 0;
}

__global__ void k_rnd(const float4* __restrict__ in, float4* __restrict__ out, int n4) {
    int i = blockIdx.x * blockDim.x + threadIdx.x;
    int stride = gridDim.x * blockDim.x;
    for (; i < n4; i += stride) {
        float4 v = in[i];
        v.x = rna_tf32(v.x); v.y = rna_tf32(v.y);
        v.z = rna_tf32(v.z); v.w = rna_tf32(v.w);
        out[i] = v;
    }
}

// gate: fp32 logits + top-3 softmax + per-expert compaction
__global__ void k_gate(const float* __restrict__ x, const float* __restrict__ gW,
                       const float* __restrict__ gb, float* __restrict__ gwout) {
    int row = blockIdx.x * 8 + (threadIdx.x >> 5);
    int lane = threadIdx.x & 31;
    const float* xr = x + (size_t)row * ND;
    float acc[NE];
    #pragma unroll
    for (int e = 0; e < NE; e++) acc[e] = 0.f;
    for (int d = lane * 4; d < ND; d += 128) {
        float4 xv = *(const float4*)(xr + d);
        #pragma unroll
        for (int e = 0; e < NE; e++) {
            float4 wv = *(const float4*)(gW + (size_t)e * ND + d);
            acc[e] += xv.x * wv.x + xv.y * wv.y + xv.z * wv.z + xv.w * wv.w;
        }
    }
    #pragma unroll
    for (int e = 0; e < NE; e++)
        #pragma unroll
        for (int o = 16; o > 0; o >>= 1)
            acc[e] += __shfl_xor_sync(0xFFFFFFFF, acc[e], o);
    float l[NE];
    #pragma unroll
    for (int e = 0; e < NE; e++) l[e] = acc[e] + gb[e];
    bool used[NE] = {false, false, false, false, false, false};
    float mx = -3.4e38f;
    for (int t = 0; t < 3; t++) {
        float best = -3.4e38f; int bi = 0;
        #pragma unroll
        for (int e = 0; e < NE; e++)
            if (!used[e] && l[e] > best) { best = l[e]; bi = e; }
        used[bi] = true;
        if (t == 0) mx = best;
    }
    float s = 0.f;
    #pragma unroll
    for (int e = 0; e < NE; e++) if (used[e]) s += expf(l[e] - mx);
    float inv = 1.f / s;
    if (lane < NE)
        gwout[(size_t)row * NE + lane] = used[lane] ? expf(l[lane] - mx) * inv : 0.f;
    if (lane == 0) {
        int t = 0;
        #pragma unroll
        for (int e = 0; e < NE; e++)
            if (used[e]) {
                int i = atomicAdd(&g_cnt[e], 1);
                g_rows[e * NB + i] = row;
                g_idx[row * 3 + t] = (e << 14) | i;
                t++;
            }
    }
}

// gather x rows per expert, fused with tf32 rounding -> g_xg[e][i][:]
__global__ void k_gather(const float* __restrict__ x) {
    const int e  = blockIdx.y;
    const int m0 = blockIdx.x * TM;
    if (m0 >= g_cnt[e]) return;
    const int t = threadIdx.x;            // 256 threads
    const int r = t >> 1;                 // rows handled per CTA: 128
    const int half = t & 1;               // 1024 floats each half
    int grow = g_rows[e * NB + m0 + r];
    const float4* src = (const float4*)(x + (size_t)grow * ND) + half * 256;
    float4* dst = (float4*)(g_xg + ((size_t)e * NB + m0 + r) * ND) + half * 256;
    #pragma unroll 8
    for (int j = 0; j < 256; j++) {
        float4 v = src[j];
        v.x = rna_tf32(v.x); v.y = rna_tf32(v.y);
        v.z = rna_tf32(v.z); v.w = rna_tf32(v.w);
        dst[j] = v;
    }
}

// ---------------- unified GEMM: TMA x TMA, 128x256 CTA, 64x64 warp tiles ----
// fragment loads via ldmatrix.x4 (tf32 quadrant trick)
// MODE 0: A=g_xg, B=W1r; epi: +b1, gelu, *gw, rna -> g_h
// MODE 1: A=g_h,  B=W2r; epi: bare store -> g_o
template <int MODE>
__global__ void __launch_bounds__(256, 1) k_gemm(
    const __grid_constant__ CUtensorMap amap,
    const __grid_constant__ CUtensorMap bmap,
    const float* __restrict__ bias,
    const float* __restrict__ gw,
    float* __restrict__ outp)
{
    const int e  = blockIdx.z;
    const int m0 = blockIdx.y * TM;
    const int n0 = blockIdx.x * TN;
    if (m0 >= g_cnt[e]) return;

    extern __shared__ __align__(1024) char smem[];
    const uint32_t sb = smem_u32(smem);
    const int tid  = threadIdx.x;
    const int lane = tid & 31;
    const int wid  = tid >> 5;
    const int wm = wid >> 2, wn = wid & 3;   // 2 x 4 warp grid, 64x64 tiles
    const int g = lane >> 2, t4 = lane & 3;
    const uint32_t FULL0  = sb;
    const uint32_t EMPTY0 = sb + 64;
    const int NB_DIM = (MODE == 0) ? NH : NC;   // B row-space per expert

    // ldmatrix per-lane source descriptors (quadrant addressing)
    const int lm = lane & 7;      // row within 8-row quadrant
    const int lq = lane >> 3;     // quadrant index 0..3
    const uint32_t aQ16 = 16u * (lq >> 1);   // A: col-quad byte offset
    const uint32_t bQ16 = 16u * (lq & 1);    // B: col-quad byte offset
    uint32_t aRow[4], aSw[4], bRow[4], bSw[4];
    #pragma unroll
    for (int mi = 0; mi < 4; mi++) {
        int r = wm * 64 + mi * 16 + lm + (lq & 1) * 8;
        aRow[mi] = (uint32_t)(r * 128);
        aSw[mi]  = (uint32_t)((r & 7) << 4);
    }
    #pragma unroll
    for (int j = 0; j < 4; j++) {
        int n = wn * 64 + (2 * j + (lq >> 1)) * 8 + lm;
        bRow[j] = (uint32_t)(n * 128);
        bSw[j]  = (uint32_t)((n & 7) << 4);
    }

    if (tid == 0) {
        #pragma unroll
        for (int s = 0; s < STAGES; s++) {
            MBARRIER_INIT(FULL0  + s * 8, 1);
            MBARRIER_INIT(EMPTY0 + s * 8, 8);
        }
    }
    __syncthreads();

    float acc[4][8][4];
    #pragma unroll
    for (int mi = 0; mi < 4; mi++)
        #pragma unroll
        for (int ni = 0; ni < 8; ni++)
            #pragma unroll
            for (int q = 0; q < 4; q++) acc[mi][ni][q] = 0.f;

    int se = 0, pe = 1;
    #define ISSUE(i) do { \
        MBARRIER_WAIT_PARITY_RELAXED(EMPTY0 + se * 8, pe); \
        uint32_t fb = FULL0 + se * 8; \
        MBARRIER_EXPECT_TX(fb, STAGE_BYTES); \
        uint32_t dst = sb + DATA_OFF + se * STAGE_BYTES; \
        TMA2D(dst,           &amap, (i) * TK, e * NB + m0, fb); \
        TMA2D(dst + A_BYTES, &bmap, (i) * TK, e * NB_DIM + n0, fb); \
        if (++se == STAGES) { se = 0; pe ^= 1; } \
    } while (0)

    if (tid == 0)
        for (int i = 0; i < STAGES - 1; i++) ISSUE(i);

    int sc = 0, pc = 0;
    for (int kt = 0; kt < KITERS; kt++) {
        MBARRIER_WAIT_PARITY(FULL0 + sc * 8, pc);
        if (tid == 0 && kt + STAGES - 1 < KITERS) ISSUE(kt + STAGES - 1);
        uint32_t aB = sb + DATA_OFF + sc * STAGE_BYTES;
        uint32_t bB = aB + A_BYTES;
        #pragma unroll
        for (int kk = 0; kk < 4; kk++) {
            uint32_t a[4][4], b[4][4];
            #pragma unroll
            for (int mi = 0; mi < 4; mi++)
                LDSM4(a[mi][0], a[mi][1], a[mi][2], a[mi][3],
                      aB + aRow[mi] + ((kk * 32 + aQ16) ^ aSw[mi]));
            #pragma unroll
            for (int j = 0; j < 4; j++)
                LDSM4(b[j][0], b[j][1], b[j][2], b[j][3],
                      bB + bRow[j] + ((kk * 32 + bQ16) ^ bSw[j]));
            #pragma unroll
            for (int mi = 0; mi < 4; mi++)
                #pragma unroll
                for (int ni = 0; ni < 8; ni++)
                    mma_tf32(acc[mi][ni], a[mi], &b[ni >> 1][(ni & 1) * 2]);
        }
        if (lane == 0) MBARRIER_ARRIVE(EMPTY0 + sc * 8);
        if (++sc == STAGES) { sc = 0; pc ^= 1; }
    }
    #undef ISSUE

    // ---------------- epilogue ----------------------------------------------
    if (MODE == 0) {
        #pragma unroll
        for (int mi = 0; mi < 4; mi++) {
            int i = m0 + wm * 64 + mi * 16 + g;
            int gb0 = g_rows[e * NB + i];
            int gb1 = g_rows[e * NB + i + 8];
            float gw0 = __ldg(&gw[(size_t)gb0 * NE + e]);
            float gw1 = __ldg(&gw[(size_t)gb1 * NE + e]);
            #pragma unroll
            for (int ni = 0; ni < 8; ni++) {
                int c = n0 + wn * 64 + ni * 8 + t4 * 2;
                float bb0 = __ldg(&bias[e * NH + c]);
                float bb1 = __ldg(&bias[e * NH + c + 1]);
                float v0 = rna_tf32(gelu_exact(acc[mi][ni][0] + bb0) * gw0);
                float v1 = rna_tf32(gelu_exact(acc[mi][ni][1] + bb1) * gw0);
                float v2 = rna_tf32(gelu_exact(acc[mi][ni][2] + bb0) * gw1);
                float v3 = rna_tf32(gelu_exact(acc[mi][ni][3] + bb1) * gw1);
                *(float2*)(outp + ((size_t)e * NB + i) * NH + c)     = make_float2(v0, v1);
                *(float2*)(outp + ((size_t)e * NB + i + 8) * NH + c) = make_float2(v2, v3);
            }
        }
    } else {
        #pragma unroll
        for (int mi = 0; mi < 4; mi++) {
            int i = m0 + wm * 64 + mi * 16 + g;
            #pragma unroll
            for (int ni = 0; ni < 8; ni++) {
                int c = n0 + wn * 64 + ni * 8 + t4 * 2;
                *(float2*)(outp + ((size_t)e * NB + i) * NC + c) =
                    make_float2(acc[mi][ni][0], acc[mi][ni][1]);
                *(float2*)(outp + ((size_t)e * NB + i + 8) * NC + c) =
                    make_float2(acc[mi][ni][2], acc[mi][ni][3]);
            }
        }
    }
}

// ---------------- combine: gather top-3 expert outputs + bias ---------------
__global__ void k_comb(const float* __restrict__ gw, const float* __restrict__ b2,
                       float* __restrict__ out) {
    int b = blockIdx.x;
    int t = threadIdx.x;
    const float4* go4 = (const float4*)g_o;
    const float4* b24 = (const float4*)b2;
    float4 a = make_float4(0.f, 0.f, 0.f, 0.f);
    #pragma unroll
    for (int tt = 0; tt < 3; tt++) {
        int v = g_idx[b * 3 + tt];
        int e = v >> 14, i = v & 16383;
        float4 s = go4[(((size_t)e * NB + i) * NC >> 2) + t];
        float w = __ldg(&gw[(size_t)b * NE + e]);
        float4 bb = b24[((size_t)e * NC >> 2) + t];
        a.x += s.x + w * bb.x;
        a.y += s.y + w * bb.y;
        a.z += s.z + w * bb.z;
        a.w += s.w + w * bb.w;
    }
    ((float4*)out)[(size_t)b * (NC / 4) + t] = a;
}

// ---------------- host ------------------------------------------------------
typedef CUresult (*EncFn)(CUtensorMap*, CUtensorMapDataType, cuuint32_t, void*,
                          const cuuint64_t*, const cuuint64_t*, const cuuint32_t*,
                          const cuuint32_t*, CUtensorMapInterleave, CUtensorMapSwizzle,
                          CUtensorMapL2promotion, CUtensorMapFloatOOBfill);

static void make2d(EncFn enc, CUtensorMap* m, void* ptr,
                   uint64_t d0, uint64_t d1, uint32_t b0, uint32_t b1) {
    cuuint64_t dims[2] = {d0, d1};
    cuuint64_t strides[1] = {d0 * 4};
    cuuint32_t box[2] = {b0, b1};
    cuuint32_t es[2] = {1, 1};
    enc(m, CU_TENSOR_MAP_DATA_TYPE_FLOAT32, 2, ptr, dims, strides, box, es,
        CU_TENSOR_MAP_INTERLEAVE_NONE, CU_TENSOR_MAP_SWIZZLE_128B,
        CU_TENSOR_MAP_L2_PROMOTION_L2_128B, CU_TENSOR_MAP_FLOAT_OOB_FILL_NONE);
}

extern "C" void kernel_launch(void* const* d_in, const int* in_sizes, int n_in,
                              void* d_out, int out_size) {
    const float* x  = (const float*)d_in[0];
    const float* gW = (const float*)d_in[1];
    const float* gb = (const float*)d_in[2];
    const float* W1 = (const float*)d_in[3];
    const float* b1 = (const float*)d_in[4];
    const float* W2 = (const float*)d_in[5];
    const float* b2 = (const float*)d_in[6];
    float* out   = (float*)d_out;
    float* gwbuf = out + (size_t)NB * NC;     // gw region of the output tuple

    void *p_xg, *p_w1, *p_w2, *p_h, *p_o;
    cudaGetSymbolAddress(&p_xg, g_xg);
    cudaGetSymbolAddress(&p_w1, g_w1r);
    cudaGetSymbolAddress(&p_w2, g_w2r);
    cudaGetSymbolAddress(&p_h,  g_h);
    cudaGetSymbolAddress(&p_o,  g_o);

    void* sym = nullptr;
    cudaDriverEntryPointQueryResult qr;
    cudaGetDriverEntryPointByVersion("cuTensorMapEncodeTiled", &sym, 12000,
                                     cudaEnableDefault, &qr);
    EncFn enc = (EncFn)sym;

    CUtensorMap mA1, mB1, mA2, mB2;
    make2d(enc, &mA1, p_xg, ND, (uint64_t)NE*NB, TK, TM);  // x gathered [E*NB, D]
    make2d(enc, &mB1, p_w1, ND, NEH,             TK, TN);  // W1 [E*H, D]
    make2d(enc, &mA2, p_h,  NH, (uint64_t)NE*NB, TK, TM);  // h_c [E*NB, H]
    make2d(enc, &mB2, p_w2, NH, (uint64_t)NE*NC, TK, TN);  // W2 [E*C, H]

    cudaFuncSetAttribute(k_gemm<0>, cudaFuncAttributeMaxDynamicSharedMemorySize, SMEM_TOTAL);
    cudaFuncSetAttribute(k_gemm<1>, cudaFuncAttributeMaxDynamicSharedMemorySize, SMEM_TOTAL);

    k_zero<<<(NE * NB + 255) / 256, 256>>>();
    k_rnd<<<4096, 256>>>((const float4*)W1, (float4*)p_w1, (int)((size_t)NEH * ND / 4));
    k_rnd<<<4096, 256>>>((const float4*)W2, (float4*)p_w2, (int)((size_t)NE * NC * NH / 4));
    k_gate<<<NB / 8, 256>>>(x, gW, gb, gwbuf);
    k_gather<<<dim3(NB / TM, NE), 256>>>(x);

    k_gemm<0><<<dim3(NH / TN, NB / TM, NE), 256, SMEM_TOTAL>>>(
        mA1, mB1, b1, gwbuf, (float*)p_h);
    k_gemm<1><<<dim3(NC / TN, NB / TM, NE), 256, SMEM_TOTAL>>>(
        mA2, mB2, b2, gwbuf, (float*)p_o);
    k_comb<<<NB, 256>>>(gwbuf, b2, out);
}

// round 9
// speedup vs baseline: 3.6094x; 1.6651x over previous
#include <cuda_runtime.h>
#include <cuda.h>
#include <cuda_fp16.h>
#include <cstdint>
#include <math.h>

// ---------------- problem dims ----------------
#define NB 16384
#define ND 2048
#define NH 2048
#define NE 6
#define NC 1024
#define NEH 12288       // E*H
// ---------------- tiling ----------------------
#define TM 128
#define TN 256
#define TK 64                      // k halfs per stage = 128 bytes
#define STAGES 4
#define A_BYTES (TM*TK*2)          // 16384
#define B_BYTES (TN*TK*2)          // 32768
#define STAGE_BYTES (A_BYTES + B_BYTES)     // 49152
#define DATA_OFF 1024
#define SMEM_TOTAL (DATA_OFF + STAGES*STAGE_BYTES)   // 197632
#define KITERS 32                  // both GEMMs: 2048/64

// ---------------- scratch (device globals; no allocation) -----------------
__device__ __half g_xg [(size_t)NE * NB * ND]; // gathered x per expert (fp16)
__device__ __half g_w1h[(size_t)NEH * ND];     // W1 fp16, [E*H, D] K-major
__device__ __half g_w2h[(size_t)NE * NC * NH]; // W2 fp16, native [E,C,H] K-major
__device__ __half g_h  [(size_t)NE * NB * NH]; // compact gw-scaled gelu(xW1+b1)
__device__ float  g_o  [(size_t)NE * NB * NC]; // compact expert outputs
__device__ int    g_rows[NE * NB];             // per-expert compacted row lists
__device__ int    g_cnt [NE];
__device__ int    g_idx [NB * 3];              // per row: (e<<14)|i  x3

// ---------------- ptx helpers ----------------------------------------------
__device__ __forceinline__ uint32_t smem_u32(const void* p) {
    uint32_t a;
    asm("{ .reg .u64 t; cvta.to.shared.u64 t, %1; cvt.u32.u64 %0, t; }"
        : "=r"(a) : "l"(p));
    return a;
}

#define LDSM4(r0, r1, r2, r3, addr) \
    asm volatile("ldmatrix.sync.aligned.m8n8.x4.shared.b16 {%0,%1,%2,%3}, [%4];" \
        : "=r"(r0), "=r"(r1), "=r"(r2), "=r"(r3) : "r"((uint32_t)(addr)))

#define MBARRIER_INIT(addr, count) \
    asm volatile("mbarrier.init.shared.b64 [%0], %1;" \
        :: "r"((uint32_t)(addr)), "r"((uint32_t)(count)) : "memory")
#define MBARRIER_EXPECT_TX(addr, bytes) \
    asm volatile("mbarrier.arrive.expect_tx.shared.b64 _, [%0], %1;" \
        :: "r"((uint32_t)(addr)), "r"((uint32_t)(bytes)) : "memory")
#define MBARRIER_ARRIVE(addr) \
    asm volatile("mbarrier.arrive.shared.b64 _, [%0];" \
        :: "r"((uint32_t)(addr)) : "memory")

#define MBARRIER_WAIT_PARITY(mbar_smem_addr, phase_parity) do { \
    uint32_t _mbar = (uint32_t)(mbar_smem_addr); \
    uint32_t _parity = (uint32_t)(phase_parity); \
    uint32_t _done; \
    asm volatile("{\n\t.reg .pred p;\n\t" \
        "mbarrier.try_wait.parity.acquire.cta.shared::cta.b64 p, [%1], %2;\n\t" \
        "selp.b32 %0, 1, 0, p;\n\t}" \
        : "=r"(_done) : "r"(_mbar), "r"(_parity) : "memory"); \
    if (!_done) { \
        asm volatile("{\n\t.reg .pred P1;\n\t" \
            "WAIT_LOOP_%=:\n\t" \
            "mbarrier.try_wait.parity.acquire.cta.shared::cta.b64 P1, [%0], %1, 0x989680;\n\t" \
            "@P1 bra.uni WAIT_DONE_%=;\n\t" \
            "bra.uni WAIT_LOOP_%=;\n\t" \
            "WAIT_DONE_%=:\n\t}" \
            :: "r"(_mbar), "r"(_parity) : "memory"); \
    } \
} while (0)

#define MBARRIER_WAIT_PARITY_RELAXED(mbar_smem_addr, phase_parity) do { \
    uint32_t _mbar = (uint32_t)(mbar_smem_addr); \
    uint32_t _parity = (uint32_t)(phase_parity); \
    uint32_t _done; \
    asm volatile("{\n\t.reg .pred p;\n\t" \
        "mbarrier.try_wait.parity.relaxed.cta.shared::cta.b64 p, [%1], %2, 0x989680;\n\t" \
        "selp.b32 %0, 1, 0, p;\n\t}" \
        : "=r"(_done) : "r"(_mbar), "r"(_parity) : "memory"); \
    if (!_done) { \
        asm volatile("{\n\t.reg .pred P1;\n\t" \
            "WAIT_LOOP_%=:\n\t" \
            "mbarrier.try_wait.parity.relaxed.cta.shared::cta.b64 P1, [%0], %1, 0x989680;\n\t" \
            "@P1 bra.uni WAIT_DONE_%=;\n\t" \
            "bra.uni WAIT_LOOP_%=;\n\t" \
            "WAIT_DONE_%=:\n\t}" \
            :: "r"(_mbar), "r"(_parity) : "memory"); \
    } \
} while (0)

#define TMA2D(smem_addr, map_ptr, cx, cy, mbar) \
    asm volatile("cp.async.bulk.tensor.2d.shared::cta.global.tile.mbarrier::complete_tx::bytes " \
        "[%0], [%1, {%2, %3}], [%4];" \
        :: "r"((uint32_t)(smem_addr)), "l"(map_ptr), "r"((int)(cx)), "r"((int)(cy)), \
           "r"((uint32_t)(mbar)) : "memory")

// m16n8k16 fp16 HMMA, fp32 accumulate, D += A*B
__device__ __forceinline__ void mma_f16(float* d, const uint32_t* a, const uint32_t* b) {
    asm volatile("mma.sync.aligned.m16n8k16.row.col.f32.f16.f16.f32 "
        "{%0,%1,%2,%3}, {%4,%5,%6,%7}, {%8,%9}, {%0,%1,%2,%3};"
        : "+f"(d[0]), "+f"(d[1]), "+f"(d[2]), "+f"(d[3])
        : "r"(a[0]), "r"(a[1]), "r"(a[2]), "r"(a[3]), "r"(b[0]), "r"(b[1]));
}

__device__ __forceinline__ float gelu_exact(float x) {
    return 0.5f * x * (1.f + erff(x * 0.70710678118654752f));
}
__device__ __forceinline__ uint32_t pack_h2(float a, float b) {
    __half2 h = __floats2half2_rn(a, b);
    return *(uint32_t*)&h;
}

// ---------------- small kernels ---------------------------------------------
__global__ void k_zero() {
    int i = blockIdx.x * blockDim.x + threadIdx.x;
    if (i < NE) g_cnt[i] = 0;
    if (i < NE * NB) g_rows[i] = 0;
}

// float4 -> 4 fp16 (rn) conversion, grid-stride
__global__ void k_cvt(const float4* __restrict__ in, uint2* __restrict__ out, int n4) {
    int i = blockIdx.x * blockDim.x + threadIdx.x;
    int stride = gridDim.x * blockDim.x;
    for (; i < n4; i += stride) {
        float4 v = in[i];
        uint2 r;
        r.x = pack_h2(v.x, v.y);
        r.y = pack_h2(v.z, v.w);
        out[i] = r;
    }
}

// gate: fp32 logits + top-3 softmax + per-expert compaction
__global__ void k_gate(const float* __restrict__ x, const float* __restrict__ gW,
                       const float* __restrict__ gb, float* __restrict__ gwout) {
    int row = blockIdx.x * 8 + (threadIdx.x >> 5);
    int lane = threadIdx.x & 31;
    const float* xr = x + (size_t)row * ND;
    float acc[NE];
    #pragma unroll
    for (int e = 0; e < NE; e++) acc[e] = 0.f;
    for (int d = lane * 4; d < ND; d += 128) {
        float4 xv = *(const float4*)(xr + d);
        #pragma unroll
        for (int e = 0; e < NE; e++) {
            float4 wv = *(const float4*)(gW + (size_t)e * ND + d);
            acc[e] += xv.x * wv.x + xv.y * wv.y + xv.z * wv.z + xv.w * wv.w;
        }
    }
    #pragma unroll
    for (int e = 0; e < NE; e++)
        #pragma unroll
        for (int o = 16; o > 0; o >>= 1)
            acc[e] += __shfl_xor_sync(0xFFFFFFFF, acc[e], o);
    float l[NE];
    #pragma unroll
    for (int e = 0; e < NE; e++) l[e] = acc[e] + gb[e];
    bool used[NE] = {false, false, false, false, false, false};
    float mx = -3.4e38f;
    for (int t = 0; t < 3; t++) {
        float best = -3.4e38f; int bi = 0;
        #pragma unroll
        for (int e = 0; e < NE; e++)
            if (!used[e] && l[e] > best) { best = l[e]; bi = e; }
        used[bi] = true;
        if (t == 0) mx = best;
    }
    float s = 0.f;
    #pragma unroll
    for (int e = 0; e < NE; e++) if (used[e]) s += expf(l[e] - mx);
    float inv = 1.f / s;
    if (lane < NE)
        gwout[(size_t)row * NE + lane] = used[lane] ? expf(l[lane] - mx) * inv : 0.f;
    if (lane == 0) {
        int t = 0;
        #pragma unroll
        for (int e = 0; e < NE; e++)
            if (used[e]) {
                int i = atomicAdd(&g_cnt[e], 1);
                g_rows[e * NB + i] = row;
                g_idx[row * 3 + t] = (e << 14) | i;
                t++;
            }
    }
}

// gather x rows per expert, fused with fp16 conversion -> g_xg[e][i][:]
__global__ void k_gather(const float* __restrict__ x) {
    const int e  = blockIdx.y;
    const int m0 = blockIdx.x * TM;
    if (m0 >= g_cnt[e]) return;
    const int t = threadIdx.x;            // 256 threads, 2 per row
    const int r = t >> 1;
    const int hf = t & 1;                 // 1024 halfs each half-row
    int grow = g_rows[e * NB + m0 + r];
    const float4* src = (const float4*)(x + (size_t)grow * ND) + hf * 256;
    uint2* dst = (uint2*)(g_xg + ((size_t)e * NB + m0 + r) * ND) + hf * 256;
    #pragma unroll 8
    for (int j = 0; j < 256; j++) {
        float4 v = src[j];
        uint2 o;
        o.x = pack_h2(v.x, v.y);
        o.y = pack_h2(v.z, v.w);
        dst[j] = o;
    }
}

// ---------------- unified GEMM: fp16 TMA x TMA, 128x256 CTA, 64x64 warps ----
// MODE 0: A=g_xg, B=W1h; epi: +b1, gelu, *gw, fp16 -> g_h
// MODE 1: A=g_h,  B=W2h; epi: bare fp32 store -> g_o
template <int MODE>
__global__ void __launch_bounds__(256, 1) k_gemm(
    const __grid_constant__ CUtensorMap amap,
    const __grid_constant__ CUtensorMap bmap,
    const float* __restrict__ bias,
    const float* __restrict__ gw,
    void* __restrict__ outp)
{
    const int e  = blockIdx.z;
    const int m0 = blockIdx.y * TM;
    const int n0 = blockIdx.x * TN;
    if (m0 >= g_cnt[e]) return;

    extern __shared__ __align__(1024) char smem[];
    const uint32_t sb = smem_u32(smem);
    const int tid  = threadIdx.x;
    const int lane = tid & 31;
    const int wid  = tid >> 5;
    const int wm = wid >> 2, wn = wid & 3;   // 2 x 4 warp grid, 64x64 tiles
    const int g = lane >> 2, t4 = lane & 3;
    const uint32_t FULL0  = sb;
    const uint32_t EMPTY0 = sb + 64;
    const int NB_DIM = (MODE == 0) ? NH : NC;   // B row-space per expert

    // ldmatrix per-lane address components (fp16-native tiles)
    // A 16x16 tile: lanes 0-15 -> rows, byte col +0; lanes 16-31 -> rows, +16
    const uint32_t aQ = 16u * (lane >> 4);
    uint32_t aRow[4], aSw[4];
    #pragma unroll
    for (int mi = 0; mi < 4; mi++) {
        int r = wm * 64 + mi * 16 + (lane & 15);
        aRow[mi] = (uint32_t)(r * 128);
        aSw[mi]  = (uint32_t)((r & 7) << 4);
    }
    // B: two n8k16 frags per LDSM4: m0=(n0-7,k0-7) m1=(n0-7,k8-15) m2=(n8-15,k0-7) m3=(n8-15,k8-15)
    const uint32_t bQ = 16u * ((lane >> 3) & 1);
    uint32_t bRow[4], bSw[4];
    #pragma unroll
    for (int j = 0; j < 4; j++) {
        int n = wn * 64 + j * 16 + (lane & 7) + 8 * ((lane >> 4) & 1);
        bRow[j] = (uint32_t)(n * 128);
        bSw[j]  = (uint32_t)((n & 7) << 4);
    }

    if (tid == 0) {
        #pragma unroll
        for (int s = 0; s < STAGES; s++) {
            MBARRIER_INIT(FULL0  + s * 8, 1);
            MBARRIER_INIT(EMPTY0 + s * 8, 8);
        }
    }
    __syncthreads();

    float acc[4][8][4];
    #pragma unroll
    for (int mi = 0; mi < 4; mi++)
        #pragma unroll
        for (int ni = 0; ni < 8; ni++)
            #pragma unroll
            for (int q = 0; q < 4; q++) acc[mi][ni][q] = 0.f;

    int se = 0, pe = 1;
    #define ISSUE(i) do { \
        MBARRIER_WAIT_PARITY_RELAXED(EMPTY0 + se * 8, pe); \
        uint32_t fb = FULL0 + se * 8; \
        MBARRIER_EXPECT_TX(fb, STAGE_BYTES); \
        uint32_t dst = sb + DATA_OFF + se * STAGE_BYTES; \
        TMA2D(dst,           &amap, (i) * TK, e * NB + m0, fb); \
        TMA2D(dst + A_BYTES, &bmap, (i) * TK, e * NB_DIM + n0, fb); \
        if (++se == STAGES) { se = 0; pe ^= 1; } \
    } while (0)

    if (tid == 0)
        for (int i = 0; i < STAGES - 1; i++) ISSUE(i);

    int sc = 0, pc = 0;
    for (int kt = 0; kt < KITERS; kt++) {
        MBARRIER_WAIT_PARITY(FULL0 + sc * 8, pc);
        if (tid == 0 && kt + STAGES - 1 < KITERS) ISSUE(kt + STAGES - 1);
        uint32_t aB = sb + DATA_OFF + sc * STAGE_BYTES;
        uint32_t bB = aB + A_BYTES;
        #pragma unroll
        for (int kk = 0; kk < 4; kk++) {        // 4 x k16 chunks = TK 64
            uint32_t a[4][4], b[4][4];
            #pragma unroll
            for (int mi = 0; mi < 4; mi++)
                LDSM4(a[mi][0], a[mi][1], a[mi][2], a[mi][3],
                      aB + aRow[mi] + ((kk * 32 + aQ) ^ aSw[mi]));
            #pragma unroll
            for (int j = 0; j < 4; j++)
                LDSM4(b[j][0], b[j][1], b[j][2], b[j][3],
                      bB + bRow[j] + ((kk * 32 + bQ) ^ bSw[j]));
            #pragma unroll
            for (int mi = 0; mi < 4; mi++)
                #pragma unroll
                for (int ni = 0; ni < 8; ni++)
                    mma_f16(acc[mi][ni], a[mi], &b[ni >> 1][(ni & 1) * 2]);
        }
        if (lane == 0) MBARRIER_ARRIVE(EMPTY0 + sc * 8);
        if (++sc == STAGES) { sc = 0; pc ^= 1; }
    }
    #undef ISSUE

    // ---------------- epilogue ----------------------------------------------
    if (MODE == 0) {
        __half* hout = (__half*)outp;
        #pragma unroll
        for (int mi = 0; mi < 4; mi++) {
            int i = m0 + wm * 64 + mi * 16 + g;
            int gb0 = g_rows[e * NB + i];
            int gb1 = g_rows[e * NB + i + 8];
            float gw0 = __ldg(&gw[(size_t)gb0 * NE + e]);
            float gw1 = __ldg(&gw[(size_t)gb1 * NE + e]);
            #pragma unroll
            for (int ni = 0; ni < 8; ni++) {
                int c = n0 + wn * 64 + ni * 8 + t4 * 2;
                float bb0 = __ldg(&bias[e * NH + c]);
                float bb1 = __ldg(&bias[e * NH + c + 1]);
                uint32_t p0 = pack_h2(gelu_exact(acc[mi][ni][0] + bb0) * gw0,
                                      gelu_exact(acc[mi][ni][1] + bb1) * gw0);
                uint32_t p1 = pack_h2(gelu_exact(acc[mi][ni][2] + bb0) * gw1,
                                      gelu_exact(acc[mi][ni][3] + bb1) * gw1);
                *(uint32_t*)(hout + ((size_t)e * NB + i) * NH + c)     = p0;
                *(uint32_t*)(hout + ((size_t)e * NB + i + 8) * NH + c) = p1;
            }
        }
    } else {
        float* fout = (float*)outp;
        #pragma unroll
        for (int mi = 0; mi < 4; mi++) {
            int i = m0 + wm * 64 + mi * 16 + g;
            #pragma unroll
            for (int ni = 0; ni < 8; ni++) {
                int c = n0 + wn * 64 + ni * 8 + t4 * 2;
                *(float2*)(fout + ((size_t)e * NB + i) * NC + c) =
                    make_float2(acc[mi][ni][0], acc[mi][ni][1]);
                *(float2*)(fout + ((size_t)e * NB + i + 8) * NC + c) =
                    make_float2(acc[mi][ni][2], acc[mi][ni][3]);
            }
        }
    }
}

// ---------------- combine: gather top-3 expert outputs + bias ---------------
__global__ void k_comb(const float* __restrict__ gw, const float* __restrict__ b2,
                       float* __restrict__ out) {
    int b = blockIdx.x;
    int t = threadIdx.x;
    const float4* go4 = (const float4*)g_o;
    const float4* b24 = (const float4*)b2;
    float4 a = make_float4(0.f, 0.f, 0.f, 0.f);
    #pragma unroll
    for (int tt = 0; tt < 3; tt++) {
        int v = g_idx[b * 3 + tt];
        int e = v >> 14, i = v & 16383;
        float4 s = go4[(((size_t)e * NB + i) * NC >> 2) + t];
        float w = __ldg(&gw[(size_t)b * NE + e]);
        float4 bb = b24[((size_t)e * NC >> 2) + t];
        a.x += s.x + w * bb.x;
        a.y += s.y + w * bb.y;
        a.z += s.z + w * bb.z;
        a.w += s.w + w * bb.w;
    }
    ((float4*)out)[(size_t)b * (NC / 4) + t] = a;
}

// ---------------- host ------------------------------------------------------
typedef CUresult (*EncFn)(CUtensorMap*, CUtensorMapDataType, cuuint32_t, void*,
                          const cuuint64_t*, const cuuint64_t*, const cuuint32_t*,
                          const cuuint32_t*, CUtensorMapInterleave, CUtensorMapSwizzle,
                          CUtensorMapL2promotion, CUtensorMapFloatOOBfill);

static void make2d_f16(EncFn enc, CUtensorMap* m, void* ptr,
                       uint64_t d0, uint64_t d1, uint32_t b0, uint32_t b1) {
    cuuint64_t dims[2] = {d0, d1};
    cuuint64_t strides[1] = {d0 * 2};
    cuuint32_t box[2] = {b0, b1};
    cuuint32_t es[2] = {1, 1};
    enc(m, CU_TENSOR_MAP_DATA_TYPE_FLOAT16, 2, ptr, dims, strides, box, es,
        CU_TENSOR_MAP_INTERLEAVE_NONE, CU_TENSOR_MAP_SWIZZLE_128B,
        CU_TENSOR_MAP_L2_PROMOTION_L2_128B, CU_TENSOR_MAP_FLOAT_OOB_FILL_NONE);
}

extern "C" void kernel_launch(void* const* d_in, const int* in_sizes, int n_in,
                              void* d_out, int out_size) {
    const float* x  = (const float*)d_in[0];
    const float* gW = (const float*)d_in[1];
    const float* gb = (const float*)d_in[2];
    const float* W1 = (const float*)d_in[3];
    const float* b1 = (const float*)d_in[4];
    const float* W2 = (const float*)d_in[5];
    const float* b2 = (const float*)d_in[6];
    float* out   = (float*)d_out;
    float* gwbuf = out + (size_t)NB * NC;     // gw region of the output tuple

    void *p_xg, *p_w1, *p_w2, *p_h, *p_o;
    cudaGetSymbolAddress(&p_xg, g_xg);
    cudaGetSymbolAddress(&p_w1, g_w1h);
    cudaGetSymbolAddress(&p_w2, g_w2h);
    cudaGetSymbolAddress(&p_h,  g_h);
    cudaGetSymbolAddress(&p_o,  g_o);

    void* sym = nullptr;
    cudaDriverEntryPointQueryResult qr;
    cudaGetDriverEntryPointByVersion("cuTensorMapEncodeTiled", &sym, 12000,
                                     cudaEnableDefault, &qr);
    EncFn enc = (EncFn)sym;

    CUtensorMap mA1, mB1, mA2, mB2;
    make2d_f16(enc, &mA1, p_xg, ND, (uint64_t)NE*NB, TK, TM);  // x gathered [E*NB, D]
    make2d_f16(enc, &mB1, p_w1, ND, NEH,             TK, TN);  // W1 [E*H, D]
    make2d_f16(enc, &mA2, p_h,  NH, (uint64_t)NE*NB, TK, TM);  // h_c [E*NB, H]
    make2d_f16(enc, &mB2, p_w2, NH, (uint64_t)NE*NC, TK, TN);  // W2 [E*C, H]

    cudaFuncSetAttribute(k_gemm<0>, cudaFuncAttributeMaxDynamicSharedMemorySize, SMEM_TOTAL);
    cudaFuncSetAttribute(k_gemm<1>, cudaFuncAttributeMaxDynamicSharedMemorySize, SMEM_TOTAL);

    k_zero<<<(NE * NB + 255) / 256, 256>>>();
    k_cvt<<<4096, 256>>>((const float4*)W1, (uint2*)p_w1, (int)((size_t)NEH * ND / 4));
    k_cvt<<<4096, 256>>>((const float4*)W2, (uint2*)p_w2, (int)((size_t)NE * NC * NH / 4));
    k_gate<<<NB / 8, 256>>>(x, gW, gb, gwbuf);
    k_gather<<<dim3(NB / TM, NE), 256>>>(x);

    k_gemm<0><<<dim3(NH / TN, NB / TM, NE), 256, SMEM_TOTAL>>>(
        mA1, mB1, b1, gwbuf, p_h);
    k_gemm<1><<<dim3(NC / TN, NB / TM, NE), 256, SMEM_TOTAL>>>(
        mA2, mB2, b2, gwbuf, p_o);
    k_comb<<<NB, 256>>>(gwbuf, b2, out);
}

// round 11
// speedup vs baseline: 3.6179x; 1.0024x over previous
#include <cuda_runtime.h>
#include <cuda.h>
#include <cuda_fp16.h>
#include <cstdint>
#include <math.h>

// ---------------- problem dims ----------------
#define NB 16384
#define ND 2048
#define NH 2048
#define NE 6
#define NC 1024
#define NEH 12288       // E*H
// ---------------- tiling ----------------------
#define TM 128
#define TN 256
#define TK 64                      // k halfs per stage = 128 bytes
#define STAGES 4
#define A_BYTES (TM*TK*2)          // 16384
#define B_BYTES (TN*TK*2)          // 32768
#define STAGE_BYTES (A_BYTES + B_BYTES)     // 49152
#define DATA_OFF 1024
#define SMEM_TOTAL (DATA_OFF + STAGES*STAGE_BYTES)   // 197632
#define KITERS 32                  // both GEMMs: 2048/64
#define KSHIFT 5
#define MAXT 40                    // max tiles per persistent CTA

// ---------------- scratch (device globals; no allocation) -----------------
__device__ __half g_xg [(size_t)NE * NB * ND]; // gathered x per expert (fp16)
__device__ __half g_w1h[(size_t)NEH * ND];     // W1 fp16, [E*H, D] K-major
__device__ __half g_w2h[(size_t)NE * NC * NH]; // W2 fp16, native [E,C,H] K-major
__device__ __half g_h  [(size_t)NE * NB * NH]; // compact gw-scaled gelu(xW1+b1)
__device__ __half g_o  [(size_t)NE * NB * NC]; // compact expert outputs (fp16)
__device__ int    g_rows[NE * NB];             // per-expert compacted row lists
__device__ int    g_cnt [NE];
__device__ int    g_idx [NB * 3];              // per row: (e<<14)|i  x3

// ---------------- ptx helpers ----------------------------------------------
__device__ __forceinline__ uint32_t smem_u32(const void* p) {
    uint32_t a;
    asm("{ .reg .u64 t; cvta.to.shared.u64 t, %1; cvt.u32.u64 %0, t; }"
        : "=r"(a) : "l"(p));
    return a;
}

#define LDSM4(r0, r1, r2, r3, addr) \
    asm volatile("ldmatrix.sync.aligned.m8n8.x4.shared.b16 {%0,%1,%2,%3}, [%4];" \
        : "=r"(r0), "=r"(r1), "=r"(r2), "=r"(r3) : "r"((uint32_t)(addr)))

#define MBARRIER_INIT(addr, count) \
    asm volatile("mbarrier.init.shared.b64 [%0], %1;" \
        :: "r"((uint32_t)(addr)), "r"((uint32_t)(count)) : "memory")
#define MBARRIER_EXPECT_TX(addr, bytes) \
    asm volatile("mbarrier.arrive.expect_tx.shared.b64 _, [%0], %1;" \
        :: "r"((uint32_t)(addr)), "r"((uint32_t)(bytes)) : "memory")
#define MBARRIER_ARRIVE(addr) \
    asm volatile("mbarrier.arrive.shared.b64 _, [%0];" \
        :: "r"((uint32_t)(addr)) : "memory")

#define MBARRIER_WAIT_PARITY(mbar_smem_addr, phase_parity) do { \
    uint32_t _mbar = (uint32_t)(mbar_smem_addr); \
    uint32_t _parity = (uint32_t)(phase_parity); \
    uint32_t _done; \
    asm volatile("{\n\t.reg .pred p;\n\t" \
        "mbarrier.try_wait.parity.acquire.cta.shared::cta.b64 p, [%1], %2;\n\t" \
        "selp.b32 %0, 1, 0, p;\n\t}" \
        : "=r"(_done) : "r"(_mbar), "r"(_parity) : "memory"); \
    if (!_done) { \
        asm volatile("{\n\t.reg .pred P1;\n\t" \
            "WAIT_LOOP_%=:\n\t" \
            "mbarrier.try_wait.parity.acquire.cta.shared::cta.b64 P1, [%0], %1, 0x989680;\n\t" \
            "@P1 bra.uni WAIT_DONE_%=;\n\t" \
            "bra.uni WAIT_LOOP_%=;\n\t" \
            "WAIT_DONE_%=:\n\t}" \
            :: "r"(_mbar), "r"(_parity) : "memory"); \
    } \
} while (0)

#define MBARRIER_WAIT_PARITY_RELAXED(mbar_smem_addr, phase_parity) do { \
    uint32_t _mbar = (uint32_t)(mbar_smem_addr); \
    uint32_t _parity = (uint32_t)(phase_parity); \
    uint32_t _done; \
    asm volatile("{\n\t.reg .pred p;\n\t" \
        "mbarrier.try_wait.parity.relaxed.cta.shared::cta.b64 p, [%1], %2, 0x989680;\n\t" \
        "selp.b32 %0, 1, 0, p;\n\t}" \
        : "=r"(_done) : "r"(_mbar), "r"(_parity) : "memory"); \
    if (!_done) { \
        asm volatile("{\n\t.reg .pred P1;\n\t" \
            "WAIT_LOOP_%=:\n\t" \
            "mbarrier.try_wait.parity.relaxed.cta.shared::cta.b64 P1, [%0], %1, 0x989680;\n\t" \
            "@P1 bra.uni WAIT_DONE_%=;\n\t" \
            "bra.uni WAIT_LOOP_%=;\n\t" \
            "WAIT_DONE_%=:\n\t}" \
            :: "r"(_mbar), "r"(_parity) : "memory"); \
    } \
} while (0)

#define TMA2D(smem_addr, map_ptr, cx, cy, mbar) \
    asm volatile("cp.async.bulk.tensor.2d.shared::cta.global.tile.mbarrier::complete_tx::bytes " \
        "[%0], [%1, {%2, %3}], [%4];" \
        :: "r"((uint32_t)(smem_addr)), "l"(map_ptr), "r"((int)(cx)), "r"((int)(cy)), \
           "r"((uint32_t)(mbar)) : "memory")

// m16n8k16 fp16 HMMA, fp32 accumulate, D += A*B
__device__ __forceinline__ void mma_f16(float* d, const uint32_t* a, const uint32_t* b) {
    asm volatile("mma.sync.aligned.m16n8k16.row.col.f32.f16.f16.f32 "
        "{%0,%1,%2,%3}, {%4,%5,%6,%7}, {%8,%9}, {%0,%1,%2,%3};"
        : "+f"(d[0]), "+f"(d[1]), "+f"(d[2]), "+f"(d[3])
        : "r"(a[0]), "r"(a[1]), "r"(a[2]), "r"(a[3]), "r"(b[0]), "r"(b[1]));
}

__device__ __forceinline__ float gelu_exact(float x) {
    return 0.5f * x * (1.f + erff(x * 0.70710678118654752f));
}
__device__ __forceinline__ uint32_t pack_h2(float a, float b) {
    __half2 h = __floats2half2_rn(a, b);
    return *(uint32_t*)&h;
}

// ---------------- small kernels ---------------------------------------------
__global__ void k_zero() {
    int i = blockIdx.x * blockDim.x + threadIdx.x;
    if (i < NE) g_cnt[i] = 0;
    if (i < NE * NB) g_rows[i] = 0;
}

// float4 -> 4 fp16 (rn) conversion, grid-stride
__global__ void k_cvt(const float4* __restrict__ in, uint2* __restrict__ out, int n4) {
    int i = blockIdx.x * blockDim.x + threadIdx.x;
    int stride = gridDim.x * blockDim.x;
    for (; i < n4; i += stride) {
        float4 v = in[i];
        uint2 r;
        r.x = pack_h2(v.x, v.y);
        r.y = pack_h2(v.z, v.w);
        out[i] = r;
    }
}

// gate: fp32 logits + top-3 softmax + per-expert compaction (dual-acc ILP)
__global__ void k_gate(const float* __restrict__ x, const float* __restrict__ gW,
                       const float* __restrict__ gb, float* __restrict__ gwout) {
    int row = blockIdx.x * 8 + (threadIdx.x >> 5);
    int lane = threadIdx.x & 31;
    const float* xr = x + (size_t)row * ND;
    float acc[NE], acc2[NE];
    #pragma unroll
    for (int e = 0; e < NE; e++) { acc[e] = 0.f; acc2[e] = 0.f; }
    for (int d = lane * 4; d < ND; d += 256) {
        float4 xv  = *(const float4*)(xr + d);
        float4 xv2 = *(const float4*)(xr + d + 128);
        #pragma unroll
        for (int e = 0; e < NE; e++) {
            float4 wv  = *(const float4*)(gW + (size_t)e * ND + d);
            float4 wv2 = *(const float4*)(gW + (size_t)e * ND + d + 128);
            acc[e]  += xv.x  * wv.x  + xv.y  * wv.y  + xv.z  * wv.z  + xv.w  * wv.w;
            acc2[e] += xv2.x * wv2.x + xv2.y * wv2.y + xv2.z * wv2.z + xv2.w * wv2.w;
        }
    }
    #pragma unroll
    for (int e = 0; e < NE; e++) {
        acc[e] += acc2[e];
        #pragma unroll
        for (int o = 16; o > 0; o >>= 1)
            acc[e] += __shfl_xor_sync(0xFFFFFFFF, acc[e], o);
    }
    float l[NE];
    #pragma unroll
    for (int e = 0; e < NE; e++) l[e] = acc[e] + gb[e];
    bool used[NE] = {false, false, false, false, false, false};
    float mx = -3.4e38f;
    for (int t = 0; t < 3; t++) {
        float best = -3.4e38f; int bi = 0;
        #pragma unroll
        for (int e = 0; e < NE; e++)
            if (!used[e] && l[e] > best) { best = l[e]; bi = e; }
        used[bi] = true;
        if (t == 0) mx = best;
    }
    float s = 0.f;
    #pragma unroll
    for (int e = 0; e < NE; e++) if (used[e]) s += expf(l[e] - mx);
    float inv = 1.f / s;
    if (lane < NE)
        gwout[(size_t)row * NE + lane] = used[lane] ? expf(l[lane] - mx) * inv : 0.f;
    if (lane == 0) {
        int t = 0;
        #pragma unroll
        for (int e = 0; e < NE; e++)
            if (used[e]) {
                int i = atomicAdd(&g_cnt[e], 1);
                g_rows[e * NB + i] = row;
                g_idx[row * 3 + t] = (e << 14) | i;
                t++;
            }
    }
}

// gather x rows per expert, fused with fp16 conversion -> g_xg[e][i][:]
__global__ void k_gather(const float* __restrict__ x) {
    const int e  = blockIdx.y;
    const int m0 = blockIdx.x * TM;
    if (m0 >= g_cnt[e]) return;
    const int t = threadIdx.x;
    const int r = t >> 1;
    const int hf = t & 1;
    int grow = g_rows[e * NB + m0 + r];
    const float4* src = (const float4*)(x + (size_t)grow * ND) + hf * 256;
    uint2* dst = (uint2*)(g_xg + ((size_t)e * NB + m0 + r) * ND) + hf * 256;
    #pragma unroll 8
    for (int j = 0; j < 256; j++) {
        float4 v = src[j];
        uint2 o;
        o.x = pack_h2(v.x, v.y);
        o.y = pack_h2(v.z, v.w);
        dst[j] = o;
    }
}

// ---------------- persistent GEMM: fp16, 128x256 CTA, 64x64 warp tiles ------
// The stage ring + producer cursor run continuously across tiles.
// MODE 0: A=g_xg, B=W1h; epi: +b1, gelu, *gw, fp16 -> g_h
// MODE 1: A=g_h,  B=W2h; epi: fp16 store -> g_o
template <int MODE>
__global__ void __launch_bounds__(256, 1) k_gemm(
    const __grid_constant__ CUtensorMap amap,
    const __grid_constant__ CUtensorMap bmap,
    const float* __restrict__ bias,
    const float* __restrict__ gw,
    __half* __restrict__ outp)
{
    extern __shared__ __align__(1024) char smem[];
    const uint32_t sb = smem_u32(smem);
    const int tid  = threadIdx.x;
    const int lane = tid & 31;
    const int wid  = tid >> 5;
    const int wm = wid >> 2, wn = wid & 3;   // 2 x 4 warp grid, 64x64 tiles
    const int g = lane >> 2, t4 = lane & 3;
    const uint32_t FULL0  = sb;
    const uint32_t EMPTY0 = sb + 64;
    const int NB_DIM = (MODE == 0) ? NH : NC;
    const int NTN    = (MODE == 0) ? (NH / TN) : (NC / TN);

    // ---- build this CTA's tile list (static stride over live tiles) --------
    int mt[NE];
    int tiles_total = 0;
    #pragma unroll
    for (int e = 0; e < NE; e++) {
        mt[e] = (g_cnt[e] + TM - 1) / TM;
        tiles_total += mt[e] * NTN;
    }
    int my_e[MAXT], my_m0[MAXT], my_n0[MAXT];
    int nmine = 0;
    for (int t = blockIdx.x; t < tiles_total && nmine < MAXT; t += gridDim.x) {
        int r = t, e = 0;
        while (r >= mt[e] * NTN) { r -= mt[e] * NTN; e++; }
        my_e[nmine]  = e;
        my_m0[nmine] = (r / NTN) * TM;
        my_n0[nmine] = (r % NTN) * TN;
        nmine++;
    }
    const int S = nmine * KITERS;

    // ldmatrix per-lane address components
    const uint32_t aQ = 16u * (lane >> 4);
    uint32_t aRow[4], aSw[4];
    #pragma unroll
    for (int mi = 0; mi < 4; mi++) {
        int r = wm * 64 + mi * 16 + (lane & 15);
        aRow[mi] = (uint32_t)(r * 128);
        aSw[mi]  = (uint32_t)((r & 7) << 4);
    }
    const uint32_t bQ = 16u * ((lane >> 3) & 1);
    uint32_t bRow[4], bSw[4];
    #pragma unroll
    for (int j = 0; j < 4; j++) {
        int n = wn * 64 + j * 16 + (lane & 7) + 8 * ((lane >> 4) & 1);
        bRow[j] = (uint32_t)(n * 128);
        bSw[j]  = (uint32_t)((n & 7) << 4);
    }

    if (tid == 0) {
        #pragma unroll
        for (int s = 0; s < STAGES; s++) {
            MBARRIER_INIT(FULL0  + s * 8, 1);
            MBARRIER_INIT(EMPTY0 + s * 8, 8);
        }
    }
    __syncthreads();
    if (S == 0) return;

    // producer cursor (ring slot + parity) — phase 1: first STAGES waits pass
    int se = 0, pp = 1;
    #define ISSUE_STEP(s_) do { \
        int pt_ = (s_) >> KSHIFT; \
        int pkt_ = (s_) & (KITERS - 1); \
        int pe_ = my_e[pt_]; \
        MBARRIER_WAIT_PARITY_RELAXED(EMPTY0 + se * 8, pp); \
        uint32_t fb = FULL0 + se * 8; \
        MBARRIER_EXPECT_TX(fb, STAGE_BYTES); \
        uint32_t dst = sb + DATA_OFF + se * STAGE_BYTES; \
        TMA2D(dst,           &amap, pkt_ * TK, pe_ * NB + my_m0[pt_], fb); \
        TMA2D(dst + A_BYTES, &bmap, pkt_ * TK, pe_ * NB_DIM + my_n0[pt_], fb); \
        if (++se == STAGES) { se = 0; pp ^= 1; } \
    } while (0)

    if (tid == 0) {
        int pre = (S < STAGES - 1) ? S : (STAGES - 1);
        for (int i = 0; i < pre; i++) ISSUE_STEP(i);
    }

    float acc[4][8][4];
    int ce = 0, cm0 = 0, cn0 = 0;
    int sc = 0, pc = 0;

    for (int s = 0; s < S; s++) {
        const int kt = s & (KITERS - 1);
        if (kt == 0) {
            int ct = s >> KSHIFT;
            ce = my_e[ct]; cm0 = my_m0[ct]; cn0 = my_n0[ct];
            #pragma unroll
            for (int mi = 0; mi < 4; mi++)
                #pragma unroll
                for (int ni = 0; ni < 8; ni++)
                    #pragma unroll
                    for (int q = 0; q < 4; q++) acc[mi][ni][q] = 0.f;
        }
        MBARRIER_WAIT_PARITY(FULL0 + sc * 8, pc);
        if (tid == 0 && s + STAGES - 1 < S) ISSUE_STEP(s + STAGES - 1);

        uint32_t aB = sb + DATA_OFF + sc * STAGE_BYTES;
        uint32_t bB = aB + A_BYTES;
        #pragma unroll
        for (int kk = 0; kk < 4; kk++) {
            uint32_t a[4][4], b[4][4];
            #pragma unroll
            for (int mi = 0; mi < 4; mi++)
                LDSM4(a[mi][0], a[mi][1], a[mi][2], a[mi][3],
                      aB + aRow[mi] + ((kk * 32 + aQ) ^ aSw[mi]));
            #pragma unroll
            for (int j = 0; j < 4; j++)
                LDSM4(b[j][0], b[j][1], b[j][2], b[j][3],
                      bB + bRow[j] + ((kk * 32 + bQ) ^ bSw[j]));
            #pragma unroll
            for (int mi = 0; mi < 4; mi++)
                #pragma unroll
                for (int ni = 0; ni < 8; ni++)
                    mma_f16(acc[mi][ni], a[mi], &b[ni >> 1][(ni & 1) * 2]);
        }
        if (lane == 0) MBARRIER_ARRIVE(EMPTY0 + sc * 8);
        if (++sc == STAGES) { sc = 0; pc ^= 1; }

        if (kt == KITERS - 1) {
            // -------- epilogue for tile (ce, cm0, cn0) -----------------------
            if (MODE == 0) {
                #pragma unroll
                for (int mi = 0; mi < 4; mi++) {
                    int i = cm0 + wm * 64 + mi * 16 + g;
                    int gb0 = g_rows[ce * NB + i];
                    int gb1 = g_rows[ce * NB + i + 8];
                    float gw0 = __ldg(&gw[(size_t)gb0 * NE + ce]);
                    float gw1 = __ldg(&gw[(size_t)gb1 * NE + ce]);
                    #pragma unroll
                    for (int ni = 0; ni < 8; ni++) {
                        int c = cn0 + wn * 64 + ni * 8 + t4 * 2;
                        float bb0 = __ldg(&bias[ce * NH + c]);
                        float bb1 = __ldg(&bias[ce * NH + c + 1]);
                        uint32_t p0 = pack_h2(gelu_exact(acc[mi][ni][0] + bb0) * gw0,
                                              gelu_exact(acc[mi][ni][1] + bb1) * gw0);
                        uint32_t p1 = pack_h2(gelu_exact(acc[mi][ni][2] + bb0) * gw1,
                                              gelu_exact(acc[mi][ni][3] + bb1) * gw1);
                        *(uint32_t*)(outp + ((size_t)ce * NB + i) * NH + c)     = p0;
                        *(uint32_t*)(outp + ((size_t)ce * NB + i + 8) * NH + c) = p1;
                    }
                }
            } else {
                #pragma unroll
                for (int mi = 0; mi < 4; mi++) {
                    int i = cm0 + wm * 64 + mi * 16 + g;
                    #pragma unroll
                    for (int ni = 0; ni < 8; ni++) {
                        int c = cn0 + wn * 64 + ni * 8 + t4 * 2;
                        uint32_t p0 = pack_h2(acc[mi][ni][0], acc[mi][ni][1]);
                        uint32_t p1 = pack_h2(acc[mi][ni][2], acc[mi][ni][3]);
                        *(uint32_t*)(outp + ((size_t)ce * NB + i) * NC + c)     = p0;
                        *(uint32_t*)(outp + ((size_t)ce * NB + i + 8) * NC + c) = p1;
                    }
                }
            }
        }
    }
    #undef ISSUE_STEP
}

// ---------------- combine: gather top-3 fp16 expert outputs + bias ----------
__global__ void k_comb(const float* __restrict__ gw, const float* __restrict__ b2,
                       float* __restrict__ out) {
    int b = blockIdx.x;
    int t = threadIdx.x;                       // 256 threads x 4 cols
    const float4* b24 = (const float4*)b2;
    float4 a = make_float4(0.f, 0.f, 0.f, 0.f);
    #pragma unroll
    for (int tt = 0; tt < 3; tt++) {
        int v = g_idx[b * 3 + tt];
        int e = v >> 14, i = v & 16383;
        uint2 s2 = *(const uint2*)(g_o + ((size_t)e * NB + i) * NC + t * 4);
        float2 f0 = __half22float2(*(__half2*)&s2.x);
        float2 f1 = __half22float2(*(__half2*)&s2.y);
        float w = __ldg(&gw[(size_t)b * NE + e]);
        float4 bb = b24[((size_t)e * NC >> 2) + t];
        a.x += f0.x + w * bb.x;
        a.y += f0.y + w * bb.y;
        a.z += f1.x + w * bb.z;
        a.w += f1.y + w * bb.w;
    }
    ((float4*)out)[(size_t)b * (NC / 4) + t] = a;
}

// ---------------- host ------------------------------------------------------
typedef CUresult (*EncFn)(CUtensorMap*, CUtensorMapDataType, cuuint32_t, void*,
                          const cuuint64_t*, const cuuint64_t*, const cuuint32_t*,
                          const cuuint32_t*, CUtensorMapInterleave, CUtensorMapSwizzle,
                          CUtensorMapL2promotion, CUtensorMapFloatOOBfill);

static void make2d_f16(EncFn enc, CUtensorMap* m, void* ptr,
                       uint64_t d0, uint64_t d1, uint32_t b0, uint32_t b1) {
    cuuint64_t dims[2] = {d0, d1};
    cuuint64_t strides[1] = {d0 * 2};
    cuuint32_t box[2] = {b0, b1};
    cuuint32_t es[2] = {1, 1};
    enc(m, CU_TENSOR_MAP_DATA_TYPE_FLOAT16, 2, ptr, dims, strides, box, es,
        CU_TENSOR_MAP_INTERLEAVE_NONE, CU_TENSOR_MAP_SWIZZLE_128B,
        CU_TENSOR_MAP_L2_PROMOTION_L2_128B, CU_TENSOR_MAP_FLOAT_OOB_FILL_NONE);
}

extern "C" void kernel_launch(void* const* d_in, const int* in_sizes, int n_in,
                              void* d_out, int out_size) {
    const float* x  = (const float*)d_in[0];
    const float* gW = (const float*)d_in[1];
    const float* gb = (const float*)d_in[2];
    const float* W1 = (const float*)d_in[3];
    const float* b1 = (const float*)d_in[4];
    const float* W2 = (const float*)d_in[5];
    const float* b2 = (const float*)d_in[6];
    float* out   = (float*)d_out;
    float* gwbuf = out + (size_t)NB * NC;     // gw region of the output tuple

    void *p_xg, *p_w1, *p_w2, *p_h, *p_o;
    cudaGetSymbolAddress(&p_xg, g_xg);
    cudaGetSymbolAddress(&p_w1, g_w1h);
    cudaGetSymbolAddress(&p_w2, g_w2h);
    cudaGetSymbolAddress(&p_h,  g_h);
    cudaGetSymbolAddress(&p_o,  g_o);

    int dev = 0;
    cudaGetDevice(&dev);
    cudaDeviceProp prop;
    cudaGetDeviceProperties(&prop, dev);
    int nsm = prop.multiProcessorCount;

    void* sym = nullptr;
    cudaDriverEntryPointQueryResult qr;
    cudaGetDriverEntryPointByVersion("cuTensorMapEncodeTiled", &sym, 12000,
                                     cudaEnableDefault, &qr);
    EncFn enc = (EncFn)sym;

    CUtensorMap mA1, mB1, mA2, mB2;
    make2d_f16(enc, &mA1, p_xg, ND, (uint64_t)NE*NB, TK, TM);  // x gathered [E*NB, D]
    make2d_f16(enc, &mB1, p_w1, ND, NEH,             TK, TN);  // W1 [E*H, D]
    make2d_f16(enc, &mA2, p_h,  NH, (uint64_t)NE*NB, TK, TM);  // h_c [E*NB, H]
    make2d_f16(enc, &mB2, p_w2, NH, (uint64_t)NE*NC, TK, TN);  // W2 [E*C, H]

    cudaFuncSetAttribute(k_gemm<0>, cudaFuncAttributeMaxDynamicSharedMemorySize, SMEM_TOTAL);
    cudaFuncSetAttribute(k_gemm<1>, cudaFuncAttributeMaxDynamicSharedMemorySize, SMEM_TOTAL);

    k_zero<<<(NE * NB + 255) / 256, 256>>>();
    k_cvt<<<4096, 256>>>((const float4*)W1, (uint2*)p_w1, (int)((size_t)NEH * ND / 4));
    k_cvt<<<4096, 256>>>((const float4*)W2, (uint2*)p_w2, (int)((size_t)NE * NC * NH / 4));
    k_gate<<<NB / 8, 256>>>(x, gW, gb, gwbuf);
    k_gather<<<dim3(NB / TM, NE), 256>>>(x);

    k_gemm<0><<<nsm, 256, SMEM_TOTAL>>>(mA1, mB1, b1, gwbuf, (__half*)p_h);
    k_gemm<1><<<nsm, 256, SMEM_TOTAL>>>(mA2, mB2, b2, gwbuf, (__half*)p_o);
    k_comb<<<NB, 256>>>(gwbuf, b2, out);
}

// round 12
// speedup vs baseline: 4.2048x; 1.1622x over previous
#include <cuda_runtime.h>
#include <cuda.h>
#include <cuda_fp16.h>
#include <cstdint>
#include <math.h>

// ---------------- problem dims ----------------
#define NB 16384
#define ND 2048
#define NH 2048
#define NE 6
#define NC 1024
#define NEH 12288       // E*H
// ---------------- tiling ----------------------
#define TM 128
#define TN 256
#define TK 64                      // k halfs per stage = 128 bytes
#define STAGES 4
#define A_BYTES (TM*TK*2)          // 16384
#define B_BYTES (TN*TK*2)          // 32768
#define STAGE_BYTES (A_BYTES + B_BYTES)     // 49152
#define DATA_OFF 1024
#define SMEM_TOTAL (DATA_OFF + STAGES*STAGE_BYTES)   // 197632
#define KITERS 32                  // both GEMMs: 2048/64
#define KSHIFT 5
#define MAXT 40                    // max tiles per persistent CTA

// ---------------- scratch (device globals; no allocation) -----------------
__device__ __half g_xg [(size_t)NE * NB * ND]; // gathered x per expert (fp16)
__device__ __half g_w1h[(size_t)NEH * ND];     // W1 fp16, [E*H, D] K-major
__device__ __half g_w2h[(size_t)NE * NC * NH]; // W2 fp16, native [E,C,H] K-major
__device__ __half g_h  [(size_t)NE * NB * NH]; // compact gw-scaled gelu(xW1+b1)
__device__ __half g_o  [(size_t)NE * NB * NC]; // compact expert outputs (fp16)
__device__ int    g_rows[NE * NB];             // per-expert compacted row lists
__device__ int    g_cnt [NE];
__device__ int    g_idx [NB * 3];              // per row: (e<<14)|i  x3

// ---------------- ptx helpers ----------------------------------------------
__device__ __forceinline__ uint32_t smem_u32(const void* p) {
    uint32_t a;
    asm("{ .reg .u64 t; cvta.to.shared.u64 t, %1; cvt.u32.u64 %0, t; }"
        : "=r"(a) : "l"(p));
    return a;
}

#define LDSM4(r0, r1, r2, r3, addr) \
    asm volatile("ldmatrix.sync.aligned.m8n8.x4.shared.b16 {%0,%1,%2,%3}, [%4];" \
        : "=r"(r0), "=r"(r1), "=r"(r2), "=r"(r3) : "r"((uint32_t)(addr)))

#define MBARRIER_INIT(addr, count) \
    asm volatile("mbarrier.init.shared.b64 [%0], %1;" \
        :: "r"((uint32_t)(addr)), "r"((uint32_t)(count)) : "memory")
#define MBARRIER_EXPECT_TX(addr, bytes) \
    asm volatile("mbarrier.arrive.expect_tx.shared.b64 _, [%0], %1;" \
        :: "r"((uint32_t)(addr)), "r"((uint32_t)(bytes)) : "memory")
#define MBARRIER_ARRIVE(addr) \
    asm volatile("mbarrier.arrive.shared.b64 _, [%0];" \
        :: "r"((uint32_t)(addr)) : "memory")

#define MBARRIER_WAIT_PARITY(mbar_smem_addr, phase_parity) do { \
    uint32_t _mbar = (uint32_t)(mbar_smem_addr); \
    uint32_t _parity = (uint32_t)(phase_parity); \
    uint32_t _done; \
    asm volatile("{\n\t.reg .pred p;\n\t" \
        "mbarrier.try_wait.parity.acquire.cta.shared::cta.b64 p, [%1], %2;\n\t" \
        "selp.b32 %0, 1, 0, p;\n\t}" \
        : "=r"(_done) : "r"(_mbar), "r"(_parity) : "memory"); \
    if (!_done) { \
        asm volatile("{\n\t.reg .pred P1;\n\t" \
            "WAIT_LOOP_%=:\n\t" \
            "mbarrier.try_wait.parity.acquire.cta.shared::cta.b64 P1, [%0], %1, 0x989680;\n\t" \
            "@P1 bra.uni WAIT_DONE_%=;\n\t" \
            "bra.uni WAIT_LOOP_%=;\n\t" \
            "WAIT_DONE_%=:\n\t}" \
            :: "r"(_mbar), "r"(_parity) : "memory"); \
    } \
} while (0)

#define MBARRIER_WAIT_PARITY_RELAXED(mbar_smem_addr, phase_parity) do { \
    uint32_t _mbar = (uint32_t)(mbar_smem_addr); \
    uint32_t _parity = (uint32_t)(phase_parity); \
    uint32_t _done; \
    asm volatile("{\n\t.reg .pred p;\n\t" \
        "mbarrier.try_wait.parity.relaxed.cta.shared::cta.b64 p, [%1], %2, 0x989680;\n\t" \
        "selp.b32 %0, 1, 0, p;\n\t}" \
        : "=r"(_done) : "r"(_mbar), "r"(_parity) : "memory"); \
    if (!_done) { \
        asm volatile("{\n\t.reg .pred P1;\n\t" \
            "WAIT_LOOP_%=:\n\t" \
            "mbarrier.try_wait.parity.relaxed.cta.shared::cta.b64 P1, [%0], %1, 0x989680;\n\t" \
            "@P1 bra.uni WAIT_DONE_%=;\n\t" \
            "bra.uni WAIT_LOOP_%=;\n\t" \
            "WAIT_DONE_%=:\n\t}" \
            :: "r"(_mbar), "r"(_parity) : "memory"); \
    } \
} while (0)

#define TMA2D(smem_addr, map_ptr, cx, cy, mbar) \
    asm volatile("cp.async.bulk.tensor.2d.shared::cta.global.tile.mbarrier::complete_tx::bytes " \
        "[%0], [%1, {%2, %3}], [%4];" \
        :: "r"((uint32_t)(smem_addr)), "l"(map_ptr), "r"((int)(cx)), "r"((int)(cy)), \
           "r"((uint32_t)(mbar)) : "memory")

// m16n8k16 fp16 HMMA, fp32 accumulate, D += A*B
__device__ __forceinline__ void mma_f16(float* d, const uint32_t* a, const uint32_t* b) {
    asm volatile("mma.sync.aligned.m16n8k16.row.col.f32.f16.f16.f32 "
        "{%0,%1,%2,%3}, {%4,%5,%6,%7}, {%8,%9}, {%0,%1,%2,%3};"
        : "+f"(d[0]), "+f"(d[1]), "+f"(d[2]), "+f"(d[3])
        : "r"(a[0]), "r"(a[1]), "r"(a[2]), "r"(a[3]), "r"(b[0]), "r"(b[1]));
}

__device__ __forceinline__ float gelu_exact(float x) {
    return 0.5f * x * (1.f + erff(x * 0.70710678118654752f));
}
__device__ __forceinline__ uint32_t pack_h2(float a, float b) {
    __half2 h = __floats2half2_rn(a, b);
    return *(uint32_t*)&h;
}

// ---------------- small kernels ---------------------------------------------
__global__ void k_zero() {
    int i = blockIdx.x * blockDim.x + threadIdx.x;
    if (i < NE) g_cnt[i] = 0;
    if (i < NE * NB) g_rows[i] = 0;
}

// float4 -> 4 fp16 (rn) conversion, grid-stride
__global__ void k_cvt(const float4* __restrict__ in, uint2* __restrict__ out, int n4) {
    int i = blockIdx.x * blockDim.x + threadIdx.x;
    int stride = gridDim.x * blockDim.x;
    for (; i < n4; i += stride) {
        float4 v = in[i];
        uint2 r;
        r.x = pack_h2(v.x, v.y);
        r.y = pack_h2(v.z, v.w);
        out[i] = r;
    }
}

// gate + fused gather: fp32 logits, top-3 softmax, compaction, and the warp
// writes its register-resident x row (fp16) into its <=3 expert slots.
__global__ void __launch_bounds__(256) k_gate(
    const float* __restrict__ x, const float* __restrict__ gW,
    const float* __restrict__ gb, float* __restrict__ gwout) {
    int row = blockIdx.x * 8 + (threadIdx.x >> 5);
    int lane = threadIdx.x & 31;
    const float* xr = x + (size_t)row * ND;
    float4 xa[16];                 // whole row, register resident
    float acc[NE], acc2[NE];
    #pragma unroll
    for (int e = 0; e < NE; e++) { acc[e] = 0.f; acc2[e] = 0.f; }
    #pragma unroll
    for (int j = 0; j < 8; j++) {
        int d = lane * 4 + j * 256;
        float4 xv  = *(const float4*)(xr + d);
        float4 xv2 = *(const float4*)(xr + d + 128);
        xa[2 * j] = xv; xa[2 * j + 1] = xv2;
        #pragma unroll
        for (int e = 0; e < NE; e++) {
            float4 wv  = *(const float4*)(gW + (size_t)e * ND + d);
            float4 wv2 = *(const float4*)(gW + (size_t)e * ND + d + 128);
            acc[e]  += xv.x  * wv.x  + xv.y  * wv.y  + xv.z  * wv.z  + xv.w  * wv.w;
            acc2[e] += xv2.x * wv2.x + xv2.y * wv2.y + xv2.z * wv2.z + xv2.w * wv2.w;
        }
    }
    #pragma unroll
    for (int e = 0; e < NE; e++) {
        acc[e] += acc2[e];
        #pragma unroll
        for (int o = 16; o > 0; o >>= 1)
            acc[e] += __shfl_xor_sync(0xFFFFFFFF, acc[e], o);
    }
    float l[NE];
    #pragma unroll
    for (int e = 0; e < NE; e++) l[e] = acc[e] + gb[e];
    bool used[NE] = {false, false, false, false, false, false};
    float mx = -3.4e38f;
    for (int t = 0; t < 3; t++) {
        float best = -3.4e38f; int bi = 0;
        #pragma unroll
        for (int e = 0; e < NE; e++)
            if (!used[e] && l[e] > best) { best = l[e]; bi = e; }
        used[bi] = true;
        if (t == 0) mx = best;
    }
    float s = 0.f;
    #pragma unroll
    for (int e = 0; e < NE; e++) if (used[e]) s += expf(l[e] - mx);
    float inv = 1.f / s;
    if (lane < NE)
        gwout[(size_t)row * NE + lane] = used[lane] ? expf(l[lane] - mx) * inv : 0.f;

    // compaction (lane 0), then broadcast the 3 (e, i) slots
    int se3 = 0, si0 = 0, si1 = 0, si2 = 0;
    if (lane == 0) {
        int t = 0, si[3] = {0, 0, 0};
        #pragma unroll
        for (int e = 0; e < NE; e++)
            if (used[e]) {
                int i = atomicAdd(&g_cnt[e], 1);
                g_rows[e * NB + i] = row;
                g_idx[row * 3 + t] = (e << 14) | i;
                se3 |= e << (t * 5);
                si[t] = i;
                t++;
            }
        si0 = si[0]; si1 = si[1]; si2 = si[2];
    }
    se3 = __shfl_sync(0xFFFFFFFF, se3, 0);
    si0 = __shfl_sync(0xFFFFFFFF, si0, 0);
    si1 = __shfl_sync(0xFFFFFFFF, si1, 0);
    si2 = __shfl_sync(0xFFFFFFFF, si2, 0);
    int sis[3] = {si0, si1, si2};

    // fused gather: write fp16 row into the 3 expert slots (from registers)
    uint2 xh[16];
    #pragma unroll
    for (int j = 0; j < 16; j++) {
        xh[j].x = pack_h2(xa[j].x, xa[j].y);
        xh[j].y = pack_h2(xa[j].z, xa[j].w);
    }
    #pragma unroll
    for (int t = 0; t < 3; t++) {
        int e = (se3 >> (t * 5)) & 31;
        __half* dst = g_xg + ((size_t)e * NB + sis[t]) * ND;
        #pragma unroll
        for (int j = 0; j < 16; j++) {
            int d = lane * 4 + (j & 1) * 128 + (j >> 1) * 256;
            *(uint2*)(dst + d) = xh[j];
        }
    }
}

// ---------------- persistent GEMM: fp16, 128x256 CTA, 64x64 warp tiles ------
// double-buffered ldmatrix fragments; early empty-arrive after last stage read.
// MODE 0: A=g_xg, B=W1h; epi: +b1, gelu, *gw, fp16 -> g_h
// MODE 1: A=g_h,  B=W2h; epi: fp16 store -> g_o
template <int MODE>
__global__ void __launch_bounds__(256, 1) k_gemm(
    const __grid_constant__ CUtensorMap amap,
    const __grid_constant__ CUtensorMap bmap,
    const float* __restrict__ bias,
    const float* __restrict__ gw,
    __half* __restrict__ outp)
{
    extern __shared__ __align__(1024) char smem[];
    const uint32_t sb = smem_u32(smem);
    const int tid  = threadIdx.x;
    const int lane = tid & 31;
    const int wid  = tid >> 5;
    const int wm = wid >> 2, wn = wid & 3;   // 2 x 4 warp grid, 64x64 tiles
    const int g = lane >> 2, t4 = lane & 3;
    const uint32_t FULL0  = sb;
    const uint32_t EMPTY0 = sb + 64;
    const int NB_DIM = (MODE == 0) ? NH : NC;
    const int NTN    = (MODE == 0) ? (NH / TN) : (NC / TN);

    // ---- build this CTA's tile list (static stride over live tiles) --------
    int mt[NE];
    int tiles_total = 0;
    #pragma unroll
    for (int e = 0; e < NE; e++) {
        mt[e] = (g_cnt[e] + TM - 1) / TM;
        tiles_total += mt[e] * NTN;
    }
    int my_e[MAXT], my_m0[MAXT], my_n0[MAXT];
    int nmine = 0;
    for (int t = blockIdx.x; t < tiles_total && nmine < MAXT; t += gridDim.x) {
        int r = t, e = 0;
        while (r >= mt[e] * NTN) { r -= mt[e] * NTN; e++; }
        my_e[nmine]  = e;
        my_m0[nmine] = (r / NTN) * TM;
        my_n0[nmine] = (r % NTN) * TN;
        nmine++;
    }
    const int S = nmine * KITERS;

    // ldmatrix per-lane address components
    const uint32_t aQ = 16u * (lane >> 4);
    uint32_t aRow[4], aSw[4];
    #pragma unroll
    for (int mi = 0; mi < 4; mi++) {
        int r = wm * 64 + mi * 16 + (lane & 15);
        aRow[mi] = (uint32_t)(r * 128);
        aSw[mi]  = (uint32_t)((r & 7) << 4);
    }
    const uint32_t bQ = 16u * ((lane >> 3) & 1);
    uint32_t bRow[4], bSw[4];
    #pragma unroll
    for (int j = 0; j < 4; j++) {
        int n = wn * 64 + j * 16 + (lane & 7) + 8 * ((lane >> 4) & 1);
        bRow[j] = (uint32_t)(n * 128);
        bSw[j]  = (uint32_t)((n & 7) << 4);
    }

    if (tid == 0) {
        #pragma unroll
        for (int s = 0; s < STAGES; s++) {
            MBARRIER_INIT(FULL0  + s * 8, 1);
            MBARRIER_INIT(EMPTY0 + s * 8, 8);
        }
    }
    __syncthreads();
    if (S == 0) return;

    // producer cursor (ring slot + parity) — phase 1: first STAGES waits pass
    int se = 0, pp = 1;
    #define ISSUE_STEP(s_) do { \
        int pt_ = (s_) >> KSHIFT; \
        int pkt_ = (s_) & (KITERS - 1); \
        int pe_ = my_e[pt_]; \
        MBARRIER_WAIT_PARITY_RELAXED(EMPTY0 + se * 8, pp); \
        uint32_t fb = FULL0 + se * 8; \
        MBARRIER_EXPECT_TX(fb, STAGE_BYTES); \
        uint32_t dst = sb + DATA_OFF + se * STAGE_BYTES; \
        TMA2D(dst,           &amap, pkt_ * TK, pe_ * NB + my_m0[pt_], fb); \
        TMA2D(dst + A_BYTES, &bmap, pkt_ * TK, pe_ * NB_DIM + my_n0[pt_], fb); \
        if (++se == STAGES) { se = 0; pp ^= 1; } \
    } while (0)

    if (tid == 0) {
        int pre = (S < STAGES - 1) ? S : (STAGES - 1);
        for (int i = 0; i < pre; i++) ISSUE_STEP(i);
    }

    float acc[4][8][4];
    int ce = 0, cm0 = 0, cn0 = 0;
    int sc = 0, pc = 0;

    #define LOADF(buf, kk) do { \
        _Pragma("unroll") \
        for (int mi = 0; mi < 4; mi++) \
            LDSM4(a[buf][mi][0], a[buf][mi][1], a[buf][mi][2], a[buf][mi][3], \
                  aB + aRow[mi] + (((kk) * 32 + aQ) ^ aSw[mi])); \
        _Pragma("unroll") \
        for (int j = 0; j < 4; j++) \
            LDSM4(b[buf][j][0], b[buf][j][1], b[buf][j][2], b[buf][j][3], \
                  bB + bRow[j] + (((kk) * 32 + bQ) ^ bSw[j])); \
    } while (0)

    for (int s = 0; s < S; s++) {
        const int kt = s & (KITERS - 1);
        if (kt == 0) {
            int ct = s >> KSHIFT;
            ce = my_e[ct]; cm0 = my_m0[ct]; cn0 = my_n0[ct];
            #pragma unroll
            for (int mi = 0; mi < 4; mi++)
                #pragma unroll
                for (int ni = 0; ni < 8; ni++)
                    #pragma unroll
                    for (int q = 0; q < 4; q++) acc[mi][ni][q] = 0.f;
        }
        MBARRIER_WAIT_PARITY(FULL0 + sc * 8, pc);
        if (tid == 0 && s + STAGES - 1 < S) ISSUE_STEP(s + STAGES - 1);

        uint32_t aB = sb + DATA_OFF + sc * STAGE_BYTES;
        uint32_t bB = aB + A_BYTES;
        uint32_t a[2][4][4], b[2][4][4];
        LOADF(0, 0);
        #pragma unroll
        for (int kk = 0; kk < 4; kk++) {
            const int cur = kk & 1;
            if (kk < 3) {
                LOADF(cur ^ 1, kk + 1);
            } else if (lane == 0) {
                MBARRIER_ARRIVE(EMPTY0 + sc * 8);   // stage fully read
            }
            #pragma unroll
            for (int mi = 0; mi < 4; mi++)
                #pragma unroll
                for (int ni = 0; ni < 8; ni++)
                    mma_f16(acc[mi][ni], a[cur][mi], &b[cur][ni >> 1][(ni & 1) * 2]);
        }
        if (++sc == STAGES) { sc = 0; pc ^= 1; }

        if (kt == KITERS - 1) {
            // -------- epilogue for tile (ce, cm0, cn0) -----------------------
            if (MODE == 0) {
                #pragma unroll
                for (int mi = 0; mi < 4; mi++) {
                    int i = cm0 + wm * 64 + mi * 16 + g;
                    int gb0 = g_rows[ce * NB + i];
                    int gb1 = g_rows[ce * NB + i + 8];
                    float gw0 = __ldg(&gw[(size_t)gb0 * NE + ce]);
                    float gw1 = __ldg(&gw[(size_t)gb1 * NE + ce]);
                    #pragma unroll
                    for (int ni = 0; ni < 8; ni++) {
                        int c = cn0 + wn * 64 + ni * 8 + t4 * 2;
                        float bb0 = __ldg(&bias[ce * NH + c]);
                        float bb1 = __ldg(&bias[ce * NH + c + 1]);
                        uint32_t p0 = pack_h2(gelu_exact(acc[mi][ni][0] + bb0) * gw0,
                                              gelu_exact(acc[mi][ni][1] + bb1) * gw0);
                        uint32_t p1 = pack_h2(gelu_exact(acc[mi][ni][2] + bb0) * gw1,
                                              gelu_exact(acc[mi][ni][3] + bb1) * gw1);
                        *(uint32_t*)(outp + ((size_t)ce * NB + i) * NH + c)     = p0;
                        *(uint32_t*)(outp + ((size_t)ce * NB + i + 8) * NH + c) = p1;
                    }
                }
            } else {
                #pragma unroll
                for (int mi = 0; mi < 4; mi++) {
                    int i = cm0 + wm * 64 + mi * 16 + g;
                    #pragma unroll
                    for (int ni = 0; ni < 8; ni++) {
                        int c = cn0 + wn * 64 + ni * 8 + t4 * 2;
                        uint32_t p0 = pack_h2(acc[mi][ni][0], acc[mi][ni][1]);
                        uint32_t p1 = pack_h2(acc[mi][ni][2], acc[mi][ni][3]);
                        *(uint32_t*)(outp + ((size_t)ce * NB + i) * NC + c)     = p0;
                        *(uint32_t*)(outp + ((size_t)ce * NB + i + 8) * NC + c) = p1;
                    }
                }
            }
        }
    }
    #undef ISSUE_STEP
    #undef LOADF
}

// ---------------- combine: gather top-3 fp16 expert outputs + bias ----------
__global__ void k_comb(const float* __restrict__ gw, const float* __restrict__ b2,
                       float* __restrict__ out) {
    int b = blockIdx.x;
    int t = threadIdx.x;                       // 256 threads x 4 cols
    const float4* b24 = (const float4*)b2;
    float4 a = make_float4(0.f, 0.f, 0.f, 0.f);
    #pragma unroll
    for (int tt = 0; tt < 3; tt++) {
        int v = g_idx[b * 3 + tt];
        int e = v >> 14, i = v & 16383;
        uint2 s2 = *(const uint2*)(g_o + ((size_t)e * NB + i) * NC + t * 4);
        float2 f0 = __half22float2(*(__half2*)&s2.x);
        float2 f1 = __half22float2(*(__half2*)&s2.y);
        float w = __ldg(&gw[(size_t)b * NE + e]);
        float4 bb = b24[((size_t)e * NC >> 2) + t];
        a.x += f0.x + w * bb.x;
        a.y += f0.y + w * bb.y;
        a.z += f1.x + w * bb.z;
        a.w += f1.y + w * bb.w;
    }
    ((float4*)out)[(size_t)b * (NC / 4) + t] = a;
}

// ---------------- host ------------------------------------------------------
typedef CUresult (*EncFn)(CUtensorMap*, CUtensorMapDataType, cuuint32_t, void*,
                          const cuuint64_t*, const cuuint64_t*, const cuuint32_t*,
                          const cuuint32_t*, CUtensorMapInterleave, CUtensorMapSwizzle,
                          CUtensorMapL2promotion, CUtensorMapFloatOOBfill);

static void make2d_f16(EncFn enc, CUtensorMap* m, void* ptr,
                       uint64_t d0, uint64_t d1, uint32_t b0, uint32_t b1) {
    cuuint64_t dims[2] = {d0, d1};
    cuuint64_t strides[1] = {d0 * 2};
    cuuint32_t box[2] = {b0, b1};
    cuuint32_t es[2] = {1, 1};
    enc(m, CU_TENSOR_MAP_DATA_TYPE_FLOAT16, 2, ptr, dims, strides, box, es,
        CU_TENSOR_MAP_INTERLEAVE_NONE, CU_TENSOR_MAP_SWIZZLE_128B,
        CU_TENSOR_MAP_L2_PROMOTION_L2_128B, CU_TENSOR_MAP_FLOAT_OOB_FILL_NONE);
}

extern "C" void kernel_launch(void* const* d_in, const int* in_sizes, int n_in,
                              void* d_out, int out_size) {
    const float* x  = (const float*)d_in[0];
    const float* gW = (const float*)d_in[1];
    const float* gb = (const float*)d_in[2];
    const float* W1 = (const float*)d_in[3];
    const float* b1 = (const float*)d_in[4];
    const float* W2 = (const float*)d_in[5];
    const float* b2 = (const float*)d_in[6];
    float* out   = (float*)d_out;
    float* gwbuf = out + (size_t)NB * NC;     // gw region of the output tuple

    void *p_xg, *p_w1, *p_w2, *p_h, *p_o;
    cudaGetSymbolAddress(&p_xg, g_xg);
    cudaGetSymbolAddress(&p_w1, g_w1h);
    cudaGetSymbolAddress(&p_w2, g_w2h);
    cudaGetSymbolAddress(&p_h,  g_h);
    cudaGetSymbolAddress(&p_o,  g_o);

    int dev = 0;
    cudaGetDevice(&dev);
    cudaDeviceProp prop;
    cudaGetDeviceProperties(&prop, dev);
    int nsm = prop.multiProcessorCount;

    void* sym = nullptr;
    cudaDriverEntryPointQueryResult qr;
    cudaGetDriverEntryPointByVersion("cuTensorMapEncodeTiled", &sym, 12000,
                                     cudaEnableDefault, &qr);
    EncFn enc = (EncFn)sym;

    CUtensorMap mA1, mB1, mA2, mB2;
    make2d_f16(enc, &mA1, p_xg, ND, (uint64_t)NE*NB, TK, TM);  // x gathered [E*NB, D]
    make2d_f16(enc, &mB1, p_w1, ND, NEH,             TK, TN);  // W1 [E*H, D]
    make2d_f16(enc, &mA2, p_h,  NH, (uint64_t)NE*NB, TK, TM);  // h_c [E*NB, H]
    make2d_f16(enc, &mB2, p_w2, NH, (uint64_t)NE*NC, TK, TN);  // W2 [E*C, H]

    cudaFuncSetAttribute(k_gemm<0>, cudaFuncAttributeMaxDynamicSharedMemorySize, SMEM_TOTAL);
    cudaFuncSetAttribute(k_gemm<1>, cudaFuncAttributeMaxDynamicSharedMemorySize, SMEM_TOTAL);

    k_zero<<<(NE * NB + 255) / 256, 256>>>();
    k_cvt<<<4096, 256>>>((const float4*)W1, (uint2*)p_w1, (int)((size_t)NEH * ND / 4));
    k_cvt<<<4096, 256>>>((const float4*)W2, (uint2*)p_w2, (int)((size_t)NE * NC * NH / 4));
    k_gate<<<NB / 8, 256>>>(x, gW, gb, gwbuf);

    k_gemm<0><<<nsm, 256, SMEM_TOTAL>>>(mA1, mB1, b1, gwbuf, (__half*)p_h);
    k_gemm<1><<<nsm, 256, SMEM_TOTAL>>>(mA2, mB2, b2, gwbuf, (__half*)p_o);
    k_comb<<<NB, 256>>>(gwbuf, b2, out);
}